// round 11
// baseline (speedup 1.0000x reference)
#include <cuda_runtime.h>
#include <cuda_bf16.h>

#define NN 1024
#define HH 96
#define EE 16384
#define TJ 64
#define BI 8

// ---------------- device scratch (no allocation allowed) ----------------
__device__ float g_xA[NN * HH];
__device__ float g_xB[NN * HH];
__device__ float g_m[NN * HH];
__device__ float g_hip[NN * HH];   // 0.5*(x@Wa1[:, :H].T + ba1)
__device__ float g_hjp[NN * HH];   // 0.5*(x@Wa1[:, H:].T)
__device__ int   g_off[NN + 1];
__device__ int   g_csr[EE];
// transposed weights (coalesced loads)
__device__ float g_TWih[HH * 288]; // [k][gate*96+h]
__device__ float g_TWhh[HH * 288];
__device__ float g_TA[HH * 192];
__device__ float g_TO1[HH * HH];
__device__ float g_TO2[HH * HH];

__device__ __forceinline__ float sigf(float v) {
    return __fdividef(1.0f, 1.0f + __expf(-v));
}
__device__ __forceinline__ float leakyf(float v) {
    return v >= 0.0f ? v : 0.01f * v;
}
__device__ __forceinline__ float tanhfast(float v) {
    float y;
    asm("tanh.approx.f32 %0, %1;" : "=f"(y) : "f"(v));
    return y;
}

// ---------------- K0: weight transpose + input projection ---------------
__global__ void k_setup(const float* __restrict__ x,
                        const float* __restrict__ Wi, const float* __restrict__ bi,
                        const float* __restrict__ Wih, const float* __restrict__ Whh,
                        const float* __restrict__ Wa1,
                        const float* __restrict__ Wo1, const float* __restrict__ Wo2) {
    int b = blockIdx.x, t = threadIdx.x;
    if (b < HH) {
        int k = b;
        g_TWih[k * 288 + t] = Wih[t * HH + k];
        g_TWhh[k * 288 + t] = Whh[t * HH + k];
        if (t < 192)
            g_TA[k * 192 + t] = (t < HH) ? Wa1[t * 192 + k]
                                         : Wa1[(t - HH) * 192 + HH + k];
        if (t < HH) {
            g_TO1[k * HH + t] = Wo1[t * HH + k];
            g_TO2[k * HH + t] = Wo2[t * HH + k];
        }
    } else {
        int rr = t / HH, h = t - rr * HH;
        int i = (b - HH) * 3 + rr;
        if (i < NN) {
            float a = bi[h];
#pragma unroll
            for (int c = 0; c < 9; c++) a = fmaf(x[i * 10 + c], Wi[h * 9 + c], a);
            g_xA[i * HH + h] = leakyf(a);
        }
    }
}

// ---------------- K1: degree count + scan + CSR fill, one block ---------
__global__ void k_scanfill(const int* __restrict__ ei) {
    __shared__ int cnt[NN];
    __shared__ int cur[NN];
    __shared__ int wsum[32];
    int t = threadIdx.x, lane = t & 31, wid = t >> 5;
    cnt[t] = 0;
    __syncthreads();
    for (int e = t; e < EE; e += NN) atomicAdd(&cnt[ei[EE + e]], 1);
    __syncthreads();
    int d = cnt[t], v = d;
#pragma unroll
    for (int o = 1; o < 32; o <<= 1) {
        int u = __shfl_up_sync(0xffffffffu, v, o);
        if (lane >= o) v += u;
    }
    if (lane == 31) wsum[wid] = v;
    __syncthreads();
    if (wid == 0) {
        int s = wsum[lane];
#pragma unroll
        for (int o = 1; o < 32; o <<= 1) {
            int u = __shfl_up_sync(0xffffffffu, s, o);
            if (lane >= o) s += u;
        }
        wsum[lane] = s;
    }
    __syncthreads();
    int incl = v + (wid ? wsum[wid - 1] : 0);
    g_off[t + 1] = incl;
    if (t == 0) g_off[0] = 0;
    cur[t] = incl - d;
    __syncthreads();
    for (int e = t; e < EE; e += NN) {
        int s = ei[e], tg = ei[EE + e];
        int p = atomicAdd(&cur[tg], 1);
        g_csr[p] = s;
    }
}

// ---------------- K2: m = x @ W_ggc, 2 rows, 288 thr (3 k-segments) -----
__global__ void __launch_bounds__(288) k_mggc(int sel, const float* __restrict__ Wg) {
    const float* xc = sel ? g_xB : g_xA;
    int i0 = blockIdx.x * 2, t = threadIdx.x;
    int h = t % HH, g = t / HH;            // g in 0..2 -> k in [g*32, g*32+32)
    __shared__ float xs[2][HH];
    __shared__ float part[3][2][HH];
    if (t < 2 * HH) {
        int r = t / HH, h2 = t - r * HH;
        xs[r][h2] = xc[(i0 + r) * HH + h2];
    }
    __syncthreads();
    float a[2] = {0.f, 0.f};
    int k0 = g * 32;
#pragma unroll 8
    for (int kk = 0; kk < 32; kk++) {
        int k = k0 + kk;
        float wv = Wg[k * HH + h];
#pragma unroll
        for (int r = 0; r < 2; r++) a[r] = fmaf(xs[r][k], wv, a[r]);
    }
#pragma unroll
    for (int r = 0; r < 2; r++) part[g][r][h] = a[r];
    __syncthreads();
    if (t < 2 * HH) {
        int r = t / HH, h2 = t - r * HH;
        g_m[(i0 + r) * HH + h2] = part[0][r][h2] + part[1][r][h2] + part[2][r][h2];
    }
}

// ---------------- K3: GRU + projections, 2 rows, 288 threads ------------
// thread t owns gate-row t (g = t/96 in {r,z,n}, h = t%96)
__global__ void __launch_bounds__(288) k_gruproj(int sel,
                          const float* __restrict__ bih, const float* __restrict__ bhh,
                          const float* __restrict__ ba1) {
    float* xc = sel ? g_xB : g_xA;
    float* xn = sel ? g_xA : g_xB;
    int i0 = blockIdx.x * 2, t = threadIdx.x;
    int h = t % HH, g = t / HH;
    __shared__ float ag[2][HH], xs[2][HH];
    __shared__ float gA[2][288];   // r,z: combined sums; n: inn part
    __shared__ float gN[2][HH];    // n: hn part
    // 384 tasks: f<192 gather (2-acc), f>=192 x-load
    for (int f = t; f < 4 * HH; f += 288) {
        if (f < 2 * HH) {
            int r = f / HH, h2 = f - r * HH;
            int row = i0 + r;
            int beg = g_off[row], end = g_off[row + 1];
            float s0 = 0.0f, s1 = 0.0f;
            int e = beg;
            for (; e + 1 < end; e += 2) {
                s0 += g_m[g_csr[e] * HH + h2];
                s1 += g_m[g_csr[e + 1] * HH + h2];
            }
            if (e < end) s0 += g_m[g_csr[e] * HH + h2];
            int d = end - beg;
            ag[r][h2] = __fdividef(s0 + s1, (float)(d > 1 ? d : 1));
        } else {
            int f2 = f - 2 * HH;
            int r = f2 / HH, h2 = f2 - r * HH;
            xs[r][h2] = xc[(i0 + r) * HH + h2];
        }
    }
    __syncthreads();
    float acc_i[2] = {0.f, 0.f};
    float acc_h[2] = {0.f, 0.f};
#pragma unroll 4
    for (int k = 0; k < HH; k++) {
        float wi = g_TWih[k * 288 + t];
        float wh = g_TWhh[k * 288 + t];
#pragma unroll
        for (int r = 0; r < 2; r++) {
            acc_i[r] = fmaf(ag[r][k], wi, acc_i[r]);
            acc_h[r] = fmaf(xs[r][k], wh, acc_h[r]);
        }
    }
    if (g < 2) {
        float bb = bih[g * HH + h] + bhh[g * HH + h];
#pragma unroll
        for (int r = 0; r < 2; r++) gA[r][t] = acc_i[r] + acc_h[r] + bb;
    } else {
        float bi_n = bih[2 * HH + h], bh_n = bhh[2 * HH + h];
#pragma unroll
        for (int r = 0; r < 2; r++) {
            gA[r][t] = acc_i[r] + bi_n;
            gN[r][h] = acc_h[r] + bh_n;
        }
    }
    __syncthreads();
    // GRU nonlinearity (192 tasks); stage new x into gA[r][0..95]
    if (t < 2 * HH) {
        int r = t / HH, h2 = t - r * HH;
        float rr = sigf(gA[r][h2]);
        float zz = sigf(gA[r][HH + h2]);
        float n = tanhf(gA[r][2 * HH + h2] + rr * gN[r][h2]);
        float xv = (1.0f - zz) * n + zz * xs[r][h2];
        int row = i0 + r;
        xc[row * HH + h2] = xv;
        xn[row * HH + h2] = 0.0f;     // accumulation target for k_att
        gA[r][h2] = xv;               // staged new x for projections
    }
    __syncthreads();
    // projections on new x: 384 tasks, 4-way k-split accumulators
    for (int f = t; f < 2 * 192; f += 288) {
        int r = f / 192, c = f - r * 192;
        float a0 = 0.f, a1 = 0.f, a2 = 0.f, a3 = 0.f;
#pragma unroll 6
        for (int kk = 0; kk < 24; kk++) {
            a0 = fmaf(gA[r][kk],      g_TA[kk * 192 + c],        a0);
            a1 = fmaf(gA[r][kk + 24], g_TA[(kk + 24) * 192 + c], a1);
            a2 = fmaf(gA[r][kk + 48], g_TA[(kk + 48) * 192 + c], a2);
            a3 = fmaf(gA[r][kk + 72], g_TA[(kk + 72) * 192 + c], a3);
        }
        float acc = (a0 + a1) + (a2 + a3) + (c < HH ? ba1[c] : 0.0f);
        float v = 0.5f * acc;
        int row = i0 + r;
        if (c < HH) g_hip[row * HH + c] = v;
        else        g_hjp[row * HH + c - HH] = v;
    }
}

// ---------------- K4: attention + x = coeffs @ x, j-split 4 -------------
__global__ void __launch_bounds__(256) k_att(int sel,
                                             const int* __restrict__ adj,
                                             const float* __restrict__ Wa2,
                                             const float* __restrict__ ba2) {
    const float* xc = sel ? g_xB : g_xA;
    float* xn = sel ? g_xA : g_xB;
    const int rg = blockIdx.x >> 2;
    const int jbase = (blockIdx.x & 3) * (NN / 4);
    const int i0 = rg * BI;
    int tid = threadIdx.x, lane = tid & 31, w = tid >> 5;
    __shared__ float hi_s[BI][HH];
    __shared__ float w_s[HH];
    __shared__ float tile[TJ][HH + 1];
    __shared__ float c2[TJ][BI];
    __shared__ float bs_s;

    if (tid < HH) w_s[tid] = 0.5f * Wa2[tid];
    for (int f = tid; f < BI * HH; f += 256) {
        int il = f / HH, k = f - il * HH;
        hi_s[il][k] = g_hip[(i0 + il) * HH + k];
    }
    __syncthreads();
    if (tid == 0) {
        float s = ba2[0];
        for (int k = 0; k < HH; k++) s += w_s[k];
        bs_s = s;
    }
    __syncthreads();

    const int jl = tid >> 2, q = tid & 3;
    float wr[24];
#pragma unroll
    for (int s = 0; s < 24; s++) wr[s] = w_s[q * 24 + s];
    const float base = bs_s;

    float a0[BI], a1[BI], a2[BI];
#pragma unroll
    for (int il = 0; il < BI; il++) { a0[il] = 0.f; a1[il] = 0.f; a2[il] = 0.f; }

    for (int jt = 0; jt < NN / 4; jt += TJ) {
        for (int f = tid; f < TJ * HH; f += 256) {
            int r = f / HH, k = f - r * HH;
            tile[r][k] = g_hjp[(jbase + jt) * HH + f];
        }
        __syncthreads();
        float p[BI];
#pragma unroll
        for (int il = 0; il < BI; il++) p[il] = 0.0f;
#pragma unroll 4
        for (int s = 0; s < 24; s++) {
            int k = q * 24 + s;
            float tj = tile[jl][k];
            float ws = wr[s];
#pragma unroll
            for (int il = 0; il < BI; il++)
                p[il] = fmaf(ws, tanhfast(hi_s[il][k] + tj), p[il]);
        }
#pragma unroll
        for (int il = 0; il < BI; il++) {
            p[il] += __shfl_xor_sync(0xffffffffu, p[il], 1);
            p[il] += __shfl_xor_sync(0xffffffffu, p[il], 2);
        }
        if (q == 0) {
            int j = jbase + jt + jl;
#pragma unroll
            for (int il = 0; il < BI; il++) {
                int a = adj[(long)(i0 + il) * NN + j];
                float sv = p[il] + base;
                c2[jl][il] = a ? fmaf(0.5f, tanhfast(0.5f * sv), 0.5f) : 0.0f;
            }
        }
        __syncthreads();
        for (int f = tid; f < TJ * HH; f += 256) {
            int r = f / HH, k = f - r * HH;
            tile[r][k] = xc[(jbase + jt) * HH + f];
        }
        __syncthreads();
#pragma unroll
        for (int u = 0; u < 8; u++) {
            int jj = w * 8 + u;
            float t0 = tile[jj][lane];
            float t1 = tile[jj][lane + 32];
            float t2 = tile[jj][lane + 64];
#pragma unroll
            for (int il = 0; il < BI; il++) {
                float c = c2[jj][il];
                a0[il] = fmaf(c, t0, a0[il]);
                a1[il] = fmaf(c, t1, a1[il]);
                a2[il] = fmaf(c, t2, a2[il]);
            }
        }
        __syncthreads();
    }
    float* sa = &tile[0][0];
#pragma unroll
    for (int il = 0; il < BI; il++) {
        sa[(w * BI + il) * HH + lane] = a0[il];
        sa[(w * BI + il) * HH + lane + 32] = a1[il];
        sa[(w * BI + il) * HH + lane + 64] = a2[il];
    }
    __syncthreads();
    for (int f = tid; f < BI * HH; f += 256) {
        int il = f / HH, h = f - il * HH;
        float s = 0.0f;
#pragma unroll
        for (int ww = 0; ww < 8; ww++) s += sa[(ww * BI + il) * HH + h];
        atomicAdd(&xn[(i0 + il) * HH + h], s);
    }
}

// ---------------- K5: output head, 4 rows per block ---------------------
__global__ void k_out(int sel,
                      const float* __restrict__ bo1, const float* __restrict__ bo2,
                      const float* __restrict__ Wp1, const float* __restrict__ bp1,
                      const float* __restrict__ Wp2, const float* __restrict__ bp2,
                      float* __restrict__ out) {
    const float* xc = sel ? g_xB : g_xA;
    int i0 = blockIdx.x * 4, h = threadIdx.x, lane = h & 31, w = h >> 5;
    __shared__ float xs[4][HH], y1[4][HH], y2[4][HH];
#pragma unroll
    for (int r = 0; r < 4; r++) xs[r][h] = xc[(i0 + r) * HH + h];
    __syncthreads();
    {
        float bb = bo1[h];
        float a[4] = {bb, bb, bb, bb};
#pragma unroll 4
        for (int k = 0; k < HH; k++) {
            float wv = g_TO1[k * HH + h];
#pragma unroll
            for (int r = 0; r < 4; r++) a[r] = fmaf(xs[r][k], wv, a[r]);
        }
#pragma unroll
        for (int r = 0; r < 4; r++) y1[r][h] = leakyf(a[r]);
    }
    __syncthreads();
    {
        float bb = bo2[h];
        float a[4] = {bb, bb, bb, bb};
#pragma unroll 4
        for (int k = 0; k < HH; k++) {
            float wv = g_TO2[k * HH + h];
#pragma unroll
            for (int r = 0; r < 4; r++) a[r] = fmaf(y1[r][k], wv, a[r]);
        }
#pragma unroll
        for (int r = 0; r < 4; r++) y2[r][h] = leakyf(a[r]);
    }
    __syncthreads();
    if (w < 2) {
        const float* Wp = (w == 0) ? Wp1 : Wp2;
        float bp = (w == 0) ? bp1[0] : bp2[0];
#pragma unroll
        for (int r = 0; r < 4; r++) {
            float p = y2[r][lane] * Wp[lane] + y2[r][lane + 32] * Wp[lane + 32]
                    + y2[r][lane + 64] * Wp[lane + 64];
#pragma unroll
            for (int o = 16; o > 0; o >>= 1) p += __shfl_xor_sync(0xffffffffu, p, o);
            if (lane == 0) out[w * NN + i0 + r] = sigf(p + bp);
        }
    }
}

// ---------------- launch ----------------
extern "C" void kernel_launch(void* const* d_in, const int* in_sizes, int n_in,
                              void* d_out, int out_size) {
    const float* x      = (const float*)d_in[0];
    const int*   ei     = (const int*)d_in[1];   // int32 (JAX x64 disabled)
    const int*   adj    = (const int*)d_in[2];
    const float* W_init = (const float*)d_in[3];
    const float* b_init = (const float*)d_in[4];
    const float* W_ggc  = (const float*)d_in[5];
    const float* W_ih   = (const float*)d_in[6];
    const float* W_hh   = (const float*)d_in[7];
    const float* b_ih   = (const float*)d_in[8];
    const float* b_hh   = (const float*)d_in[9];
    const float* Wa1    = (const float*)d_in[10];
    const float* ba1    = (const float*)d_in[11];
    const float* Wa2    = (const float*)d_in[12];
    const float* ba2    = (const float*)d_in[13];
    const float* Wo1    = (const float*)d_in[14];
    const float* bo1    = (const float*)d_in[15];
    const float* Wo2    = (const float*)d_in[16];
    const float* bo2    = (const float*)d_in[17];
    const float* Wp1    = (const float*)d_in[18];
    const float* bp1    = (const float*)d_in[19];
    const float* Wp2    = (const float*)d_in[20];
    const float* bp2    = (const float*)d_in[21];
    float* out = (float*)d_out;

    k_setup<<<96 + 342, 288>>>(x, W_init, b_init, W_ih, W_hh, Wa1, Wo1, Wo2);
    k_scanfill<<<1, NN>>>(ei);

    for (int t = 0; t < 2; t++) {
        int sel = t & 1;   // x in A when t==0, in B when t==1
        k_mggc<<<NN / 2, 288>>>(sel, W_ggc);
        k_gruproj<<<NN / 2, 288>>>(sel, b_ih, b_hh, ba1);
        k_att<<<NN / BI * 4, 256>>>(sel, adj, Wa2, ba2);
    }
    k_out<<<NN / 4, HH>>>(0, bo1, bo2, Wp1, bp1, Wp2, bp2, out);
}

// round 12
// speedup vs baseline: 1.3520x; 1.3520x over previous
#include <cuda_runtime.h>
#include <cuda_bf16.h>

#define NN 1024
#define HH 96
#define EE 16384
#define TJ 64
#define BI 8
#define RG 8   // rows per block in mggc/gruproj

// ---------------- device scratch (no allocation allowed) ----------------
__device__ float g_xA[NN * HH];
__device__ float g_xB[NN * HH];
__device__ float g_m[NN * HH];
__device__ float g_hip[NN * HH];   // 0.5*(x@Wa1[:, :H].T + ba1)
__device__ float g_hjp[NN * HH];   // 0.5*(x@Wa1[:, H:].T)
__device__ int   g_off[NN + 1];
__device__ int   g_csr[EE];
// transposed weights (coalesced loads)
__device__ float g_TWih[HH * 288]; // [k][gate*96+h]
__device__ float g_TWhh[HH * 288];
__device__ float g_TA[HH * 192];
__device__ float g_TO1[HH * HH];
__device__ float g_TO2[HH * HH];

__device__ __forceinline__ float sigf(float v) {
    return __fdividef(1.0f, 1.0f + __expf(-v));
}
__device__ __forceinline__ float leakyf(float v) {
    return v >= 0.0f ? v : 0.01f * v;
}
__device__ __forceinline__ float tanhfast(float v) {
    float y;
    asm("tanh.approx.f32 %0, %1;" : "=f"(y) : "f"(v));
    return y;
}

// ---------------- K0: weight transpose + input projection ---------------
__global__ void k_setup(const float* __restrict__ x,
                        const float* __restrict__ Wi, const float* __restrict__ bi,
                        const float* __restrict__ Wih, const float* __restrict__ Whh,
                        const float* __restrict__ Wa1,
                        const float* __restrict__ Wo1, const float* __restrict__ Wo2) {
    int b = blockIdx.x, t = threadIdx.x;
    if (b < HH) {
        int k = b;
        g_TWih[k * 288 + t] = Wih[t * HH + k];
        g_TWhh[k * 288 + t] = Whh[t * HH + k];
        if (t < 192)
            g_TA[k * 192 + t] = (t < HH) ? Wa1[t * 192 + k]
                                         : Wa1[(t - HH) * 192 + HH + k];
        if (t < HH) {
            g_TO1[k * HH + t] = Wo1[t * HH + k];
            g_TO2[k * HH + t] = Wo2[t * HH + k];
        }
    } else {
        int rr = t / HH, h = t - rr * HH;
        int i = (b - HH) * 3 + rr;
        if (i < NN) {
            float a = bi[h];
#pragma unroll
            for (int c = 0; c < 9; c++) a = fmaf(x[i * 10 + c], Wi[h * 9 + c], a);
            g_xA[i * HH + h] = leakyf(a);
        }
    }
}

// ---------------- K1: degree count + scan + CSR fill, one block ---------
__global__ void k_scanfill(const int* __restrict__ ei) {
    __shared__ int cnt[NN];
    __shared__ int cur[NN];
    __shared__ int wsum[32];
    int t = threadIdx.x, lane = t & 31, wid = t >> 5;
    cnt[t] = 0;
    __syncthreads();
    for (int e = t; e < EE; e += NN) atomicAdd(&cnt[ei[EE + e]], 1);
    __syncthreads();
    int d = cnt[t], v = d;
#pragma unroll
    for (int o = 1; o < 32; o <<= 1) {
        int u = __shfl_up_sync(0xffffffffu, v, o);
        if (lane >= o) v += u;
    }
    if (lane == 31) wsum[wid] = v;
    __syncthreads();
    if (wid == 0) {
        int s = wsum[lane];
#pragma unroll
        for (int o = 1; o < 32; o <<= 1) {
            int u = __shfl_up_sync(0xffffffffu, s, o);
            if (lane >= o) s += u;
        }
        wsum[lane] = s;
    }
    __syncthreads();
    int incl = v + (wid ? wsum[wid - 1] : 0);
    g_off[t + 1] = incl;
    if (t == 0) g_off[0] = 0;
    cur[t] = incl - d;
    __syncthreads();
    for (int e = t; e < EE; e += NN) {
        int s = ei[e], tg = ei[EE + e];
        int p = atomicAdd(&cur[tg], 1);
        g_csr[p] = s;
    }
}

// ---------------- K2: m = x @ W_ggc, RG rows, 288 thr (3 k-segments) ----
__global__ void __launch_bounds__(288) k_mggc(int sel, const float* __restrict__ Wg) {
    const float* xc = sel ? g_xB : g_xA;
    int i0 = blockIdx.x * RG, t = threadIdx.x;
    int h = t % HH, g = t / HH;            // g in 0..2 -> k in [g*32, g*32+32)
    __shared__ float xs[RG][HH];
    __shared__ float part[3][RG][HH];
    for (int f = t; f < RG * HH; f += 288) {
        int r = f / HH, h2 = f - r * HH;
        xs[r][h2] = xc[(i0 + r) * HH + h2];
    }
    __syncthreads();
    float a[RG];
#pragma unroll
    for (int r = 0; r < RG; r++) a[r] = 0.0f;
    int k0 = g * 32;
#pragma unroll 4
    for (int kk = 0; kk < 32; kk++) {
        int k = k0 + kk;
        float wv = Wg[k * HH + h];
#pragma unroll
        for (int r = 0; r < RG; r++) a[r] = fmaf(xs[r][k], wv, a[r]);
    }
#pragma unroll
    for (int r = 0; r < RG; r++) part[g][r][h] = a[r];
    __syncthreads();
    for (int f = t; f < RG * HH; f += 288) {
        int r = f / HH, h2 = f - r * HH;
        g_m[(i0 + r) * HH + h2] = part[0][r][h2] + part[1][r][h2] + part[2][r][h2];
    }
}

// ---------------- K3: GRU + projections, RG rows, 288 threads -----------
// thread t owns gate-row t (g = t/96 in {r,z,n}, h = t%96)
__global__ void __launch_bounds__(288) k_gruproj(int sel,
                          const float* __restrict__ bih, const float* __restrict__ bhh,
                          const float* __restrict__ ba1) {
    float* xc = sel ? g_xB : g_xA;
    float* xn = sel ? g_xA : g_xB;
    int i0 = blockIdx.x * RG, t = threadIdx.x;
    int h = t % HH, g = t / HH;
    __shared__ float ag[RG][HH], xs[RG][HH];
    __shared__ float gA[RG][288];  // r,z: combined sums; n: inn part
    __shared__ float gN[RG][HH];   // n: hn part
    // 2*RG*96 tasks: first half gather (2-acc), second half x-load
    for (int f = t; f < 2 * RG * HH; f += 288) {
        if (f < RG * HH) {
            int r = f / HH, h2 = f - r * HH;
            int row = i0 + r;
            int beg = g_off[row], end = g_off[row + 1];
            float s0 = 0.0f, s1 = 0.0f;
            int e = beg;
            for (; e + 1 < end; e += 2) {
                s0 += g_m[g_csr[e] * HH + h2];
                s1 += g_m[g_csr[e + 1] * HH + h2];
            }
            if (e < end) s0 += g_m[g_csr[e] * HH + h2];
            int d = end - beg;
            ag[r][h2] = __fdividef(s0 + s1, (float)(d > 1 ? d : 1));
        } else {
            int f2 = f - RG * HH;
            int r = f2 / HH, h2 = f2 - r * HH;
            xs[r][h2] = xc[(i0 + r) * HH + h2];
        }
    }
    __syncthreads();
    float acc_i[RG], acc_h[RG];
#pragma unroll
    for (int r = 0; r < RG; r++) { acc_i[r] = 0.0f; acc_h[r] = 0.0f; }
#pragma unroll 2
    for (int k = 0; k < HH; k++) {
        float wi = g_TWih[k * 288 + t];
        float wh = g_TWhh[k * 288 + t];
#pragma unroll
        for (int r = 0; r < RG; r++) {
            acc_i[r] = fmaf(ag[r][k], wi, acc_i[r]);
            acc_h[r] = fmaf(xs[r][k], wh, acc_h[r]);
        }
    }
    if (g < 2) {
        float bb = bih[g * HH + h] + bhh[g * HH + h];
#pragma unroll
        for (int r = 0; r < RG; r++) gA[r][t] = acc_i[r] + acc_h[r] + bb;
    } else {
        float bi_n = bih[2 * HH + h], bh_n = bhh[2 * HH + h];
#pragma unroll
        for (int r = 0; r < RG; r++) {
            gA[r][t] = acc_i[r] + bi_n;
            gN[r][h] = acc_h[r] + bh_n;
        }
    }
    __syncthreads();
    // GRU nonlinearity (RG*96 tasks); stage new x into gA[r][0..95]
    for (int f = t; f < RG * HH; f += 288) {
        int r = f / HH, h2 = f - r * HH;
        float rr = sigf(gA[r][h2]);
        float zz = sigf(gA[r][HH + h2]);
        float n = tanhf(gA[r][2 * HH + h2] + rr * gN[r][h2]);
        float xv = (1.0f - zz) * n + zz * xs[r][h2];
        int row = i0 + r;
        xc[row * HH + h2] = xv;
        xn[row * HH + h2] = 0.0f;     // accumulation target for k_att
        gA[r][h2] = xv;               // staged new x for projections
    }
    __syncthreads();
    // projections on new x: RG*192 tasks, 4-way k-split accumulators
    for (int f = t; f < RG * 192; f += 288) {
        int r = f / 192, c = f - r * 192;
        float a0 = 0.f, a1 = 0.f, a2 = 0.f, a3 = 0.f;
#pragma unroll 6
        for (int kk = 0; kk < 24; kk++) {
            a0 = fmaf(gA[r][kk],      g_TA[kk * 192 + c],        a0);
            a1 = fmaf(gA[r][kk + 24], g_TA[(kk + 24) * 192 + c], a1);
            a2 = fmaf(gA[r][kk + 48], g_TA[(kk + 48) * 192 + c], a2);
            a3 = fmaf(gA[r][kk + 72], g_TA[(kk + 72) * 192 + c], a3);
        }
        float acc = (a0 + a1) + (a2 + a3) + (c < HH ? ba1[c] : 0.0f);
        float v = 0.5f * acc;
        int row = i0 + r;
        if (c < HH) g_hip[row * HH + c] = v;
        else        g_hjp[row * HH + c - HH] = v;
    }
}

// ---------------- K4: attention + x = coeffs @ x, j-split 2 -------------
__global__ void __launch_bounds__(256) k_att(int sel,
                                             const int* __restrict__ adj,
                                             const float* __restrict__ Wa2,
                                             const float* __restrict__ ba2) {
    const float* xc = sel ? g_xB : g_xA;
    float* xn = sel ? g_xA : g_xB;
    const int rg = blockIdx.x >> 1;
    const int jbase = (blockIdx.x & 1) * (NN / 2);
    const int i0 = rg * BI;
    int tid = threadIdx.x, lane = tid & 31, w = tid >> 5;
    __shared__ float hi_s[BI][HH];
    __shared__ float w_s[HH];
    __shared__ float tile[TJ][HH + 1];
    __shared__ float c2[TJ][BI];
    __shared__ float bs_s;

    if (tid < HH) w_s[tid] = 0.5f * Wa2[tid];
    for (int f = tid; f < BI * HH; f += 256) {
        int il = f / HH, k = f - il * HH;
        hi_s[il][k] = g_hip[(i0 + il) * HH + k];
    }
    __syncthreads();
    if (tid == 0) {
        float s = ba2[0];
        for (int k = 0; k < HH; k++) s += w_s[k];
        bs_s = s;
    }
    __syncthreads();

    const int jl = tid >> 2, q = tid & 3;
    float wr[24];
#pragma unroll
    for (int s = 0; s < 24; s++) wr[s] = w_s[q * 24 + s];
    const float base = bs_s;

    float a0[BI], a1[BI], a2[BI];
#pragma unroll
    for (int il = 0; il < BI; il++) { a0[il] = 0.f; a1[il] = 0.f; a2[il] = 0.f; }

    for (int jt = 0; jt < NN / 2; jt += TJ) {
        for (int f = tid; f < TJ * HH; f += 256) {
            int r = f / HH, k = f - r * HH;
            tile[r][k] = g_hjp[(jbase + jt) * HH + f];
        }
        __syncthreads();
        float p[BI];
#pragma unroll
        for (int il = 0; il < BI; il++) p[il] = 0.0f;
#pragma unroll 4
        for (int s = 0; s < 24; s++) {
            int k = q * 24 + s;
            float tj = tile[jl][k];
            float ws = wr[s];
#pragma unroll
            for (int il = 0; il < BI; il++)
                p[il] = fmaf(ws, tanhfast(hi_s[il][k] + tj), p[il]);
        }
#pragma unroll
        for (int il = 0; il < BI; il++) {
            p[il] += __shfl_xor_sync(0xffffffffu, p[il], 1);
            p[il] += __shfl_xor_sync(0xffffffffu, p[il], 2);
        }
        if (q == 0) {
            int j = jbase + jt + jl;
#pragma unroll
            for (int il = 0; il < BI; il++) {
                int a = adj[(long)(i0 + il) * NN + j];
                float sv = p[il] + base;
                c2[jl][il] = a ? fmaf(0.5f, tanhfast(0.5f * sv), 0.5f) : 0.0f;
            }
        }
        __syncthreads();
        for (int f = tid; f < TJ * HH; f += 256) {
            int r = f / HH, k = f - r * HH;
            tile[r][k] = xc[(jbase + jt) * HH + f];
        }
        __syncthreads();
#pragma unroll
        for (int u = 0; u < 8; u++) {
            int jj = w * 8 + u;
            float t0 = tile[jj][lane];
            float t1 = tile[jj][lane + 32];
            float t2 = tile[jj][lane + 64];
#pragma unroll
            for (int il = 0; il < BI; il++) {
                float c = c2[jj][il];
                a0[il] = fmaf(c, t0, a0[il]);
                a1[il] = fmaf(c, t1, a1[il]);
                a2[il] = fmaf(c, t2, a2[il]);
            }
        }
        __syncthreads();
    }
    float* sa = &tile[0][0];
#pragma unroll
    for (int il = 0; il < BI; il++) {
        sa[(w * BI + il) * HH + lane] = a0[il];
        sa[(w * BI + il) * HH + lane + 32] = a1[il];
        sa[(w * BI + il) * HH + lane + 64] = a2[il];
    }
    __syncthreads();
    for (int f = tid; f < BI * HH; f += 256) {
        int il = f / HH, h = f - il * HH;
        float s = 0.0f;
#pragma unroll
        for (int ww = 0; ww < 8; ww++) s += sa[(ww * BI + il) * HH + h];
        atomicAdd(&xn[(i0 + il) * HH + h], s);
    }
}

// ---------------- K5: output head, 4 rows per block ---------------------
__global__ void k_out(int sel,
                      const float* __restrict__ bo1, const float* __restrict__ bo2,
                      const float* __restrict__ Wp1, const float* __restrict__ bp1,
                      const float* __restrict__ Wp2, const float* __restrict__ bp2,
                      float* __restrict__ out) {
    const float* xc = sel ? g_xB : g_xA;
    int i0 = blockIdx.x * 4, h = threadIdx.x, lane = h & 31, w = h >> 5;
    __shared__ float xs[4][HH], y1[4][HH], y2[4][HH];
#pragma unroll
    for (int r = 0; r < 4; r++) xs[r][h] = xc[(i0 + r) * HH + h];
    __syncthreads();
    {
        float bb = bo1[h];
        float a[4] = {bb, bb, bb, bb};
#pragma unroll 4
        for (int k = 0; k < HH; k++) {
            float wv = g_TO1[k * HH + h];
#pragma unroll
            for (int r = 0; r < 4; r++) a[r] = fmaf(xs[r][k], wv, a[r]);
        }
#pragma unroll
        for (int r = 0; r < 4; r++) y1[r][h] = leakyf(a[r]);
    }
    __syncthreads();
    {
        float bb = bo2[h];
        float a[4] = {bb, bb, bb, bb};
#pragma unroll 4
        for (int k = 0; k < HH; k++) {
            float wv = g_TO2[k * HH + h];
#pragma unroll
            for (int r = 0; r < 4; r++) a[r] = fmaf(y1[r][k], wv, a[r]);
        }
#pragma unroll
        for (int r = 0; r < 4; r++) y2[r][h] = leakyf(a[r]);
    }
    __syncthreads();
    if (w < 2) {
        const float* Wp = (w == 0) ? Wp1 : Wp2;
        float bp = (w == 0) ? bp1[0] : bp2[0];
#pragma unroll
        for (int r = 0; r < 4; r++) {
            float p = y2[r][lane] * Wp[lane] + y2[r][lane + 32] * Wp[lane + 32]
                    + y2[r][lane + 64] * Wp[lane + 64];
#pragma unroll
            for (int o = 16; o > 0; o >>= 1) p += __shfl_xor_sync(0xffffffffu, p, o);
            if (lane == 0) out[w * NN + i0 + r] = sigf(p + bp);
        }
    }
}

// ---------------- launch ----------------
extern "C" void kernel_launch(void* const* d_in, const int* in_sizes, int n_in,
                              void* d_out, int out_size) {
    const float* x      = (const float*)d_in[0];
    const int*   ei     = (const int*)d_in[1];   // int32 (JAX x64 disabled)
    const int*   adj    = (const int*)d_in[2];
    const float* W_init = (const float*)d_in[3];
    const float* b_init = (const float*)d_in[4];
    const float* W_ggc  = (const float*)d_in[5];
    const float* W_ih   = (const float*)d_in[6];
    const float* W_hh   = (const float*)d_in[7];
    const float* b_ih   = (const float*)d_in[8];
    const float* b_hh   = (const float*)d_in[9];
    const float* Wa1    = (const float*)d_in[10];
    const float* ba1    = (const float*)d_in[11];
    const float* Wa2    = (const float*)d_in[12];
    const float* ba2    = (const float*)d_in[13];
    const float* Wo1    = (const float*)d_in[14];
    const float* bo1    = (const float*)d_in[15];
    const float* Wo2    = (const float*)d_in[16];
    const float* bo2    = (const float*)d_in[17];
    const float* Wp1    = (const float*)d_in[18];
    const float* bp1    = (const float*)d_in[19];
    const float* Wp2    = (const float*)d_in[20];
    const float* bp2    = (const float*)d_in[21];
    float* out = (float*)d_out;

    k_setup<<<96 + 342, 288>>>(x, W_init, b_init, W_ih, W_hh, Wa1, Wo1, Wo2);
    k_scanfill<<<1, NN>>>(ei);

    for (int t = 0; t < 2; t++) {
        int sel = t & 1;   // x in A when t==0, in B when t==1
        k_mggc<<<NN / RG, 288>>>(sel, W_ggc);
        k_gruproj<<<NN / RG, 288>>>(sel, b_ih, b_hh, ba1);
        k_att<<<NN / BI * 2, 256>>>(sel, adj, Wa2, ba2);
    }
    k_out<<<NN / 4, HH>>>(0, bo1, bo2, Wp1, bp1, Wp2, bp2, out);
}

// round 13
// speedup vs baseline: 1.6490x; 1.2196x over previous
#include <cuda_runtime.h>
#include <cuda_bf16.h>

#define NN 1024
#define HH 96
#define EE 16384
#define TJ 64
#define BI 8
#define RG 4   // rows per block in mggc/gruproj

// ---------------- device scratch (no allocation allowed) ----------------
__device__ float g_xA[NN * HH];
__device__ float g_xB[NN * HH];
__device__ float g_m[NN * HH];
__device__ float g_hip[NN * HH];   // 0.5*(x@Wa1[:, :H].T + ba1)
__device__ float g_hjp[NN * HH];   // 0.5*(x@Wa1[:, H:].T)
__device__ int   g_off[NN + 1];
__device__ int   g_csr[EE];
// transposed weights (coalesced loads)
__device__ float g_TWih[HH * 288]; // [k][gate*96+h]
__device__ float g_TWhh[HH * 288];
__device__ float g_TA[HH * 192];
__device__ float g_TO1[HH * HH];
__device__ float g_TO2[HH * HH];

__device__ __forceinline__ float sigf(float v) {
    return __fdividef(1.0f, 1.0f + __expf(-v));
}
__device__ __forceinline__ float leakyf(float v) {
    return v >= 0.0f ? v : 0.01f * v;
}
__device__ __forceinline__ float tanhfast(float v) {
    float y;
    asm("tanh.approx.f32 %0, %1;" : "=f"(y) : "f"(v));
    return y;
}

// ---------------- K0: weight transpose + input projection ---------------
__global__ void k_setup(const float* __restrict__ x,
                        const float* __restrict__ Wi, const float* __restrict__ bi,
                        const float* __restrict__ Wih, const float* __restrict__ Whh,
                        const float* __restrict__ Wa1,
                        const float* __restrict__ Wo1, const float* __restrict__ Wo2) {
    int b = blockIdx.x, t = threadIdx.x;
    if (b < HH) {
        int k = b;
        g_TWih[k * 288 + t] = Wih[t * HH + k];
        g_TWhh[k * 288 + t] = Whh[t * HH + k];
        if (t < 192)
            g_TA[k * 192 + t] = (t < HH) ? Wa1[t * 192 + k]
                                         : Wa1[(t - HH) * 192 + HH + k];
        if (t < HH) {
            g_TO1[k * HH + t] = Wo1[t * HH + k];
            g_TO2[k * HH + t] = Wo2[t * HH + k];
        }
    } else {
        int rr = t / HH, h = t - rr * HH;
        int i = (b - HH) * 3 + rr;
        if (i < NN) {
            float a = bi[h];
#pragma unroll
            for (int c = 0; c < 9; c++) a = fmaf(x[i * 10 + c], Wi[h * 9 + c], a);
            g_xA[i * HH + h] = leakyf(a);
        }
    }
}

// ---------------- K1: degree count + scan + CSR fill, one block ---------
__global__ void k_scanfill(const int* __restrict__ ei) {
    __shared__ int cnt[NN];
    __shared__ int cur[NN];
    __shared__ int wsum[32];
    int t = threadIdx.x, lane = t & 31, wid = t >> 5;
    cnt[t] = 0;
    __syncthreads();
    for (int e = t; e < EE; e += NN) atomicAdd(&cnt[ei[EE + e]], 1);
    __syncthreads();
    int d = cnt[t], v = d;
#pragma unroll
    for (int o = 1; o < 32; o <<= 1) {
        int u = __shfl_up_sync(0xffffffffu, v, o);
        if (lane >= o) v += u;
    }
    if (lane == 31) wsum[wid] = v;
    __syncthreads();
    if (wid == 0) {
        int s = wsum[lane];
#pragma unroll
        for (int o = 1; o < 32; o <<= 1) {
            int u = __shfl_up_sync(0xffffffffu, s, o);
            if (lane >= o) s += u;
        }
        wsum[lane] = s;
    }
    __syncthreads();
    int incl = v + (wid ? wsum[wid - 1] : 0);
    g_off[t + 1] = incl;
    if (t == 0) g_off[0] = 0;
    cur[t] = incl - d;
    __syncthreads();
    for (int e = t; e < EE; e += NN) {
        int s = ei[e], tg = ei[EE + e];
        int p = atomicAdd(&cur[tg], 1);
        g_csr[p] = s;
    }
}

// ---------------- K2: m = x @ W_ggc, RG rows, 288 thr, MLP prefetch -----
__global__ void __launch_bounds__(288) k_mggc(int sel, const float* __restrict__ Wg) {
    const float* xc = sel ? g_xB : g_xA;
    int i0 = blockIdx.x * RG, t = threadIdx.x;
    int h = t % HH, g = t / HH;            // g in 0..2 -> k in [g*32, g*32+32)
    __shared__ float xs[RG][HH];
    __shared__ float part[3][RG][HH];
    for (int f = t; f < RG * HH; f += 288) {
        int r = f / HH, h2 = f - r * HH;
        xs[r][h2] = xc[(i0 + r) * HH + h2];
    }
    __syncthreads();
    float a[RG];
#pragma unroll
    for (int r = 0; r < RG; r++) a[r] = 0.0f;
    int k0 = g * 32;
#pragma unroll 1
    for (int kb = 0; kb < 32; kb += 8) {
        float wbuf[8];
#pragma unroll
        for (int u = 0; u < 8; u++) wbuf[u] = Wg[(k0 + kb + u) * HH + h];
#pragma unroll
        for (int u = 0; u < 8; u++) {
            int k = k0 + kb + u;
#pragma unroll
            for (int r = 0; r < RG; r++) a[r] = fmaf(xs[r][k], wbuf[u], a[r]);
        }
    }
#pragma unroll
    for (int r = 0; r < RG; r++) part[g][r][h] = a[r];
    __syncthreads();
    for (int f = t; f < RG * HH; f += 288) {
        int r = f / HH, h2 = f - r * HH;
        g_m[(i0 + r) * HH + h2] = part[0][r][h2] + part[1][r][h2] + part[2][r][h2];
    }
}

// ---------------- K3: GRU + projections, RG rows, 288 thr, MLP prefetch -
// thread t owns gate-row t (g = t/96 in {r,z,n}, h = t%96)
__global__ void __launch_bounds__(288) k_gruproj(int sel,
                          const float* __restrict__ bih, const float* __restrict__ bhh,
                          const float* __restrict__ ba1) {
    float* xc = sel ? g_xB : g_xA;
    float* xn = sel ? g_xA : g_xB;
    int i0 = blockIdx.x * RG, t = threadIdx.x;
    int h = t % HH, g = t / HH;
    __shared__ float ag[RG][HH], xs[RG][HH];
    __shared__ float gA[RG][288];  // r,z: combined sums; n: inn part
    __shared__ float gN[RG][HH];   // n: hn part
    // 2*RG*96 tasks: first half gather (4 indep chains), second half x-load
    for (int f = t; f < 2 * RG * HH; f += 288) {
        if (f < RG * HH) {
            int r = f / HH, h2 = f - r * HH;
            int row = i0 + r;
            int beg = g_off[row], end = g_off[row + 1];
            float s0 = 0.f, s1 = 0.f, s2 = 0.f, s3 = 0.f;
            int e = beg;
            for (; e + 3 < end; e += 4) {
                int j0 = g_csr[e],     j1 = g_csr[e + 1];
                int j2 = g_csr[e + 2], j3 = g_csr[e + 3];
                s0 += g_m[j0 * HH + h2];
                s1 += g_m[j1 * HH + h2];
                s2 += g_m[j2 * HH + h2];
                s3 += g_m[j3 * HH + h2];
            }
            for (; e < end; e++) s0 += g_m[g_csr[e] * HH + h2];
            int d = end - beg;
            ag[r][h2] = __fdividef((s0 + s1) + (s2 + s3), (float)(d > 1 ? d : 1));
        } else {
            int f2 = f - RG * HH;
            int r = f2 / HH, h2 = f2 - r * HH;
            xs[r][h2] = xc[(i0 + r) * HH + h2];
        }
    }
    __syncthreads();
    float acc_i[RG], acc_h[RG];
#pragma unroll
    for (int r = 0; r < RG; r++) { acc_i[r] = 0.0f; acc_h[r] = 0.0f; }
#pragma unroll 2
    for (int kb = 0; kb < HH; kb += 8) {
        float wi[8], wh[8];
#pragma unroll
        for (int u = 0; u < 8; u++) {
            wi[u] = g_TWih[(kb + u) * 288 + t];
            wh[u] = g_TWhh[(kb + u) * 288 + t];
        }
#pragma unroll
        for (int u = 0; u < 8; u++) {
            int k = kb + u;
#pragma unroll
            for (int r = 0; r < RG; r++) {
                acc_i[r] = fmaf(ag[r][k], wi[u], acc_i[r]);
                acc_h[r] = fmaf(xs[r][k], wh[u], acc_h[r]);
            }
        }
    }
    if (g < 2) {
        float bb = bih[g * HH + h] + bhh[g * HH + h];
#pragma unroll
        for (int r = 0; r < RG; r++) gA[r][t] = acc_i[r] + acc_h[r] + bb;
    } else {
        float bi_n = bih[2 * HH + h], bh_n = bhh[2 * HH + h];
#pragma unroll
        for (int r = 0; r < RG; r++) {
            gA[r][t] = acc_i[r] + bi_n;
            gN[r][h] = acc_h[r] + bh_n;
        }
    }
    __syncthreads();
    // GRU nonlinearity (RG*96 tasks); stage new x into gA[r][0..95]
    for (int f = t; f < RG * HH; f += 288) {
        int r = f / HH, h2 = f - r * HH;
        float rr = sigf(gA[r][h2]);
        float zz = sigf(gA[r][HH + h2]);
        float n = tanhf(gA[r][2 * HH + h2] + rr * gN[r][h2]);
        float xv = (1.0f - zz) * n + zz * xs[r][h2];
        int row = i0 + r;
        xc[row * HH + h2] = xv;
        xn[row * HH + h2] = 0.0f;     // accumulation target for k_att
        gA[r][h2] = xv;               // staged new x for projections
    }
    __syncthreads();
    // projections on new x: RG*192 tasks, 8-wide weight prefetch, 4 accs
    for (int f = t; f < RG * 192; f += 288) {
        int r = f / 192, c = f - r * 192;
        float a0 = 0.f, a1 = 0.f, a2 = 0.f, a3 = 0.f;
#pragma unroll 2
        for (int kb = 0; kb < HH; kb += 8) {
            float wbuf[8];
#pragma unroll
            for (int u = 0; u < 8; u++) wbuf[u] = g_TA[(kb + u) * 192 + c];
            a0 = fmaf(gA[r][kb],     wbuf[0], a0);
            a1 = fmaf(gA[r][kb + 1], wbuf[1], a1);
            a2 = fmaf(gA[r][kb + 2], wbuf[2], a2);
            a3 = fmaf(gA[r][kb + 3], wbuf[3], a3);
            a0 = fmaf(gA[r][kb + 4], wbuf[4], a0);
            a1 = fmaf(gA[r][kb + 5], wbuf[5], a1);
            a2 = fmaf(gA[r][kb + 6], wbuf[6], a2);
            a3 = fmaf(gA[r][kb + 7], wbuf[7], a3);
        }
        float acc = (a0 + a1) + (a2 + a3) + (c < HH ? ba1[c] : 0.0f);
        float v = 0.5f * acc;
        int row = i0 + r;
        if (c < HH) g_hip[row * HH + c] = v;
        else        g_hjp[row * HH + c - HH] = v;
    }
}

// ---------------- K4: attention + x = coeffs @ x, j-split 2 -------------
__global__ void __launch_bounds__(256) k_att(int sel,
                                             const int* __restrict__ adj,
                                             const float* __restrict__ Wa2,
                                             const float* __restrict__ ba2) {
    const float* xc = sel ? g_xB : g_xA;
    float* xn = sel ? g_xA : g_xB;
    const int rg = blockIdx.x >> 1;
    const int jbase = (blockIdx.x & 1) * (NN / 2);
    const int i0 = rg * BI;
    int tid = threadIdx.x, lane = tid & 31, w = tid >> 5;
    __shared__ float hi_s[BI][HH];
    __shared__ float w_s[HH];
    __shared__ float tile[TJ][HH + 1];
    __shared__ float c2[TJ][BI];
    __shared__ float bs_s;

    if (tid < HH) w_s[tid] = 0.5f * Wa2[tid];
    for (int f = tid; f < BI * HH; f += 256) {
        int il = f / HH, k = f - il * HH;
        hi_s[il][k] = g_hip[(i0 + il) * HH + k];
    }
    __syncthreads();
    if (tid == 0) {
        float s = ba2[0];
        for (int k = 0; k < HH; k++) s += w_s[k];
        bs_s = s;
    }
    __syncthreads();

    const int jl = tid >> 2, q = tid & 3;
    float wr[24];
#pragma unroll
    for (int s = 0; s < 24; s++) wr[s] = w_s[q * 24 + s];
    const float base = bs_s;

    float a0[BI], a1[BI], a2[BI];
#pragma unroll
    for (int il = 0; il < BI; il++) { a0[il] = 0.f; a1[il] = 0.f; a2[il] = 0.f; }

    for (int jt = 0; jt < NN / 2; jt += TJ) {
        for (int f = tid; f < TJ * HH; f += 256) {
            int r = f / HH, k = f - r * HH;
            tile[r][k] = g_hjp[(jbase + jt) * HH + f];
        }
        __syncthreads();
        float p[BI];
#pragma unroll
        for (int il = 0; il < BI; il++) p[il] = 0.0f;
#pragma unroll 4
        for (int s = 0; s < 24; s++) {
            int k = q * 24 + s;
            float tj = tile[jl][k];
            float ws = wr[s];
#pragma unroll
            for (int il = 0; il < BI; il++)
                p[il] = fmaf(ws, tanhfast(hi_s[il][k] + tj), p[il]);
        }
#pragma unroll
        for (int il = 0; il < BI; il++) {
            p[il] += __shfl_xor_sync(0xffffffffu, p[il], 1);
            p[il] += __shfl_xor_sync(0xffffffffu, p[il], 2);
        }
        if (q == 0) {
            int j = jbase + jt + jl;
#pragma unroll
            for (int il = 0; il < BI; il++) {
                int a = adj[(long)(i0 + il) * NN + j];
                float sv = p[il] + base;
                c2[jl][il] = a ? fmaf(0.5f, tanhfast(0.5f * sv), 0.5f) : 0.0f;
            }
        }
        __syncthreads();
        for (int f = tid; f < TJ * HH; f += 256) {
            int r = f / HH, k = f - r * HH;
            tile[r][k] = xc[(jbase + jt) * HH + f];
        }
        __syncthreads();
#pragma unroll
        for (int u = 0; u < 8; u++) {
            int jj = w * 8 + u;
            float t0 = tile[jj][lane];
            float t1 = tile[jj][lane + 32];
            float t2 = tile[jj][lane + 64];
#pragma unroll
            for (int il = 0; il < BI; il++) {
                float c = c2[jj][il];
                a0[il] = fmaf(c, t0, a0[il]);
                a1[il] = fmaf(c, t1, a1[il]);
                a2[il] = fmaf(c, t2, a2[il]);
            }
        }
        __syncthreads();
    }
    float* sa = &tile[0][0];
#pragma unroll
    for (int il = 0; il < BI; il++) {
        sa[(w * BI + il) * HH + lane] = a0[il];
        sa[(w * BI + il) * HH + lane + 32] = a1[il];
        sa[(w * BI + il) * HH + lane + 64] = a2[il];
    }
    __syncthreads();
    for (int f = tid; f < BI * HH; f += 256) {
        int il = f / HH, h = f - il * HH;
        float s = 0.0f;
#pragma unroll
        for (int ww = 0; ww < 8; ww++) s += sa[(ww * BI + il) * HH + h];
        atomicAdd(&xn[(i0 + il) * HH + h], s);
    }
}

// ---------------- K5: output head, 4 rows per block ---------------------
__global__ void k_out(int sel,
                      const float* __restrict__ bo1, const float* __restrict__ bo2,
                      const float* __restrict__ Wp1, const float* __restrict__ bp1,
                      const float* __restrict__ Wp2, const float* __restrict__ bp2,
                      float* __restrict__ out) {
    const float* xc = sel ? g_xB : g_xA;
    int i0 = blockIdx.x * 4, h = threadIdx.x, lane = h & 31, w = h >> 5;
    __shared__ float xs[4][HH], y1[4][HH], y2[4][HH];
#pragma unroll
    for (int r = 0; r < 4; r++) xs[r][h] = xc[(i0 + r) * HH + h];
    __syncthreads();
    {
        float bb = bo1[h];
        float a[4] = {bb, bb, bb, bb};
#pragma unroll 2
        for (int kb = 0; kb < HH; kb += 8) {
            float wbuf[8];
#pragma unroll
            for (int u = 0; u < 8; u++) wbuf[u] = g_TO1[(kb + u) * HH + h];
#pragma unroll
            for (int u = 0; u < 8; u++) {
#pragma unroll
                for (int r = 0; r < 4; r++) a[r] = fmaf(xs[r][kb + u], wbuf[u], a[r]);
            }
        }
#pragma unroll
        for (int r = 0; r < 4; r++) y1[r][h] = leakyf(a[r]);
    }
    __syncthreads();
    {
        float bb = bo2[h];
        float a[4] = {bb, bb, bb, bb};
#pragma unroll 2
        for (int kb = 0; kb < HH; kb += 8) {
            float wbuf[8];
#pragma unroll
            for (int u = 0; u < 8; u++) wbuf[u] = g_TO2[(kb + u) * HH + h];
#pragma unroll
            for (int u = 0; u < 8; u++) {
#pragma unroll
                for (int r = 0; r < 4; r++) a[r] = fmaf(y1[r][kb + u], wbuf[u], a[r]);
            }
        }
#pragma unroll
        for (int r = 0; r < 4; r++) y2[r][h] = leakyf(a[r]);
    }
    __syncthreads();
    if (w < 2) {
        const float* Wp = (w == 0) ? Wp1 : Wp2;
        float bp = (w == 0) ? bp1[0] : bp2[0];
#pragma unroll
        for (int r = 0; r < 4; r++) {
            float p = y2[r][lane] * Wp[lane] + y2[r][lane + 32] * Wp[lane + 32]
                    + y2[r][lane + 64] * Wp[lane + 64];
#pragma unroll
            for (int o = 16; o > 0; o >>= 1) p += __shfl_xor_sync(0xffffffffu, p, o);
            if (lane == 0) out[w * NN + i0 + r] = sigf(p + bp);
        }
    }
}

// ---------------- launch ----------------
extern "C" void kernel_launch(void* const* d_in, const int* in_sizes, int n_in,
                              void* d_out, int out_size) {
    const float* x      = (const float*)d_in[0];
    const int*   ei     = (const int*)d_in[1];   // int32 (JAX x64 disabled)
    const int*   adj    = (const int*)d_in[2];
    const float* W_init = (const float*)d_in[3];
    const float* b_init = (const float*)d_in[4];
    const float* W_ggc  = (const float*)d_in[5];
    const float* W_ih   = (const float*)d_in[6];
    const float* W_hh   = (const float*)d_in[7];
    const float* b_ih   = (const float*)d_in[8];
    const float* b_hh   = (const float*)d_in[9];
    const float* Wa1    = (const float*)d_in[10];
    const float* ba1    = (const float*)d_in[11];
    const float* Wa2    = (const float*)d_in[12];
    const float* ba2    = (const float*)d_in[13];
    const float* Wo1    = (const float*)d_in[14];
    const float* bo1    = (const float*)d_in[15];
    const float* Wo2    = (const float*)d_in[16];
    const float* bo2    = (const float*)d_in[17];
    const float* Wp1    = (const float*)d_in[18];
    const float* bp1    = (const float*)d_in[19];
    const float* Wp2    = (const float*)d_in[20];
    const float* bp2    = (const float*)d_in[21];
    float* out = (float*)d_out;

    k_setup<<<96 + 342, 288>>>(x, W_init, b_init, W_ih, W_hh, Wa1, Wo1, Wo2);
    k_scanfill<<<1, NN>>>(ei);

    for (int t = 0; t < 2; t++) {
        int sel = t & 1;   // x in A when t==0, in B when t==1
        k_mggc<<<NN / RG, 288>>>(sel, W_ggc);
        k_gruproj<<<NN / RG, 288>>>(sel, b_ih, b_hh, ba1);
        k_att<<<NN / BI * 2, 256>>>(sel, adj, Wa2, ba2);
    }
    k_out<<<NN / 4, HH>>>(0, bo1, bo2, Wp1, bp1, Wp2, bp2, out);
}

// round 15
// speedup vs baseline: 1.7851x; 1.0825x over previous
#include <cuda_runtime.h>
#include <cuda_bf16.h>

#define NN 1024
#define HH 96
#define EE 16384
#define TJ 64
#define BI 8
#define KB 8          // k-chunk for smem staging
#define NCH (HH / KB) // 12 chunks

// ---------------- device scratch (no allocation allowed) ----------------
__device__ float g_xA[NN * HH];
__device__ float g_xB[NN * HH];
__device__ float g_xC[NN * HH];    // GRU output (k_att phase-2 source)
__device__ float g_hip[NN * HH];
__device__ float g_hjp[NN * HH];
__device__ int   g_off[NN + 1];
__device__ int   g_csr[EE];
__device__ float g_TWih[HH * 288]; // [k][gate*96+h]  (used only to build Wcomb)
__device__ float g_TWhh[HH * 288];
__device__ float g_Wc[HH * 288];   // Wcomb[k][t] = sum_j Wggc[k][j]*Wih[t][j]
__device__ float g_TA[HH * 192];
__device__ float g_TO1[HH * HH];
__device__ float g_TO2[HH * HH];

__device__ __forceinline__ float sigf(float v) {
    return __fdividef(1.0f, 1.0f + __expf(-v));
}
__device__ __forceinline__ float leakyf(float v) {
    return v >= 0.0f ? v : 0.01f * v;
}
__device__ __forceinline__ float tanhfast(float v) {
    float y;
    asm("tanh.approx.f32 %0, %1;" : "=f"(y) : "f"(v));
    return y;
}

// ---------------- K0: weight transpose + input projection ---------------
__global__ void k_setup(const float* __restrict__ x,
                        const float* __restrict__ Wi, const float* __restrict__ bi,
                        const float* __restrict__ Wih, const float* __restrict__ Whh,
                        const float* __restrict__ Wa1,
                        const float* __restrict__ Wo1, const float* __restrict__ Wo2) {
    int b = blockIdx.x, t = threadIdx.x;
    if (b < HH) {
        int k = b;
        g_TWih[k * 288 + t] = Wih[t * HH + k];
        g_TWhh[k * 288 + t] = Whh[t * HH + k];
        if (t < 192)
            g_TA[k * 192 + t] = (t < HH) ? Wa1[t * 192 + k]
                                         : Wa1[(t - HH) * 192 + HH + k];
        if (t < HH) {
            g_TO1[k * HH + t] = Wo1[t * HH + k];
            g_TO2[k * HH + t] = Wo2[t * HH + k];
        }
    } else {
        int rr = t / HH, h = t - rr * HH;
        int i = (b - HH) * 3 + rr;
        if (i < NN) {
            float a = bi[h];
#pragma unroll
            for (int c = 0; c < 9; c++) a = fmaf(x[i * 10 + c], Wi[h * 9 + c], a);
            g_xA[i * HH + h] = leakyf(a);
        }
    }
}

// ---------------- K0b: Wcomb = Wggc @ Wih^T (needs TWih) ----------------
__global__ void k_wcomb(const float* __restrict__ Wg) {
    int k = blockIdx.x, t = threadIdx.x;
    __shared__ float swg[HH];
    if (t < HH) swg[t] = Wg[k * HH + t];
    __syncthreads();
    float acc = 0.0f;
#pragma unroll 2
    for (int jb = 0; jb < HH; jb += 8) {
        float wv[8];
#pragma unroll
        for (int u = 0; u < 8; u++) wv[u] = g_TWih[(jb + u) * 288 + t];
#pragma unroll
        for (int u = 0; u < 8; u++) acc = fmaf(swg[jb + u], wv[u], acc);
    }
    g_Wc[k * 288 + t] = acc;
}

// ---------------- K1: degree count + scan + CSR fill, one block ---------
__global__ void k_scanfill(const int* __restrict__ ei) {
    __shared__ int cnt[NN];
    __shared__ int cur[NN];
    __shared__ int wsum[32];
    int t = threadIdx.x, lane = t & 31, wid = t >> 5;
    cnt[t] = 0;
    __syncthreads();
    for (int e = t; e < EE; e += NN) atomicAdd(&cnt[ei[EE + e]], 1);
    __syncthreads();
    int d = cnt[t], v = d;
#pragma unroll
    for (int o = 1; o < 32; o <<= 1) {
        int u = __shfl_up_sync(0xffffffffu, v, o);
        if (lane >= o) v += u;
    }
    if (lane == 31) wsum[wid] = v;
    __syncthreads();
    if (wid == 0) {
        int s = wsum[lane];
#pragma unroll
        for (int o = 1; o < 32; o <<= 1) {
            int u = __shfl_up_sync(0xffffffffu, s, o);
            if (lane >= o) s += u;
        }
        wsum[lane] = s;
    }
    __syncthreads();
    int incl = v + (wid ? wsum[wid - 1] : 0);
    g_off[t + 1] = incl;
    if (t == 0) g_off[0] = 0;
    cur[t] = incl - d;
    __syncthreads();
    for (int e = t; e < EE; e += NN) {
        int s = ei[e], tg = ei[EE + e];
        int p = atomicAdd(&cur[tg], 1);
        g_csr[p] = s;
    }
}

// ---------------- K2: gather + GRU + projections, smem-staged GEMMs -----
// 4 rows/block, grid 256, 288 threads. Thread t = gate-column.
__global__ void __launch_bounds__(288) k_grup(int sel,
                          const float* __restrict__ bih, const float* __restrict__ bhh,
                          const float* __restrict__ ba1) {
    const float* xc = sel ? g_xB : g_xA;   // read-only this launch
    float* xn = sel ? g_xA : g_xB;         // k_att accumulation target
    int t = threadIdx.x;
    int i0 = blockIdx.x * 4;
    __shared__ __align__(16) float ys[4][HH];   // gathered mean, then xnew
    __shared__ __align__(16) float xs[4][HH];
    __shared__ __align__(16) float gA[4][288];
    __shared__ __align__(16) float gN[4][HH];
    __shared__ __align__(16) float sbuf[2 * 2 * KB * 288];  // 36864 B

    // ---- phase A: gather halves (t<192) + x loads (t>=192) ----
    float4* sP = (float4*)&gA[0][0];   // sP[seg(2)][r(4)][h4(24)]
    if (t < 192) {
        int r = t / 48, rem = t % 48, seg = rem / 24, h4 = rem % 24;
        int row = i0 + r;
        int beg = g_off[row], end = g_off[row + 1];
        int d = end - beg, mid = beg + (d >> 1);
        int s = seg ? mid : beg;
        int e = seg ? end : mid;
        float4 a0 = {0.f, 0.f, 0.f, 0.f}, a1 = {0.f, 0.f, 0.f, 0.f};
        int ee = s;
        for (; ee + 1 < e; ee += 2) {
            int j0 = g_csr[ee], j1 = g_csr[ee + 1];
            float4 v0 = ((const float4*)(xc + j0 * HH))[h4];
            float4 v1 = ((const float4*)(xc + j1 * HH))[h4];
            a0.x += v0.x; a0.y += v0.y; a0.z += v0.z; a0.w += v0.w;
            a1.x += v1.x; a1.y += v1.y; a1.z += v1.z; a1.w += v1.w;
        }
        if (ee < e) {
            int j0 = g_csr[ee];
            float4 v0 = ((const float4*)(xc + j0 * HH))[h4];
            a0.x += v0.x; a0.y += v0.y; a0.z += v0.z; a0.w += v0.w;
        }
        a0.x += a1.x; a0.y += a1.y; a0.z += a1.z; a0.w += a1.w;
        sP[(seg * 4 + r) * 24 + h4] = a0;
    } else {
        int u = t - 192;                  // 96 tasks = 4 rows x 24 f4
        int r = u / 24, h4 = u % 24;
        ((float4*)&xs[r][0])[h4] = ((const float4*)(xc + (i0 + r) * HH))[h4];
    }
    __syncthreads();
    if (t < 96) {
        int r = t / 24, h4 = t % 24;
        int row = i0 + r;
        int d = g_off[row + 1] - g_off[row];
        float inv = __fdividef(1.0f, (float)(d > 1 ? d : 1));
        float4 a = sP[(0 * 4 + r) * 24 + h4];
        float4 b = sP[(1 * 4 + r) * 24 + h4];
        float4 o;
        o.x = (a.x + b.x) * inv; o.y = (a.y + b.y) * inv;
        o.z = (a.z + b.z) * inv; o.w = (a.w + b.w) * inv;
        ((float4*)&ys[r][0])[h4] = o;
    }
    __syncthreads();

    // ---- phase B: gates GEMM, double-buffered weight staging ----
    // staging map: v = t + 288q in [0,1152): mat = v/576, k = (v%576)/72, c4 = v%72
    int matq[4], kq[4], c4q[4];
#pragma unroll
    for (int q = 0; q < 4; q++) {
        int v = t + 288 * q;
        matq[q] = v / 576;
        int rem = v - matq[q] * 576;
        kq[q] = rem / 72;
        c4q[q] = rem - kq[q] * 72;
    }
    {   // prologue: stage chunk 0 into buf 0
        float4 st[4];
#pragma unroll
        for (int q = 0; q < 4; q++) {
            const float* src = matq[q] ? g_TWhh : g_Wc;
            st[q] = ((const float4*)(src + kq[q] * 288))[c4q[q]];
        }
#pragma unroll
        for (int q = 0; q < 4; q++)
            ((float4*)(sbuf + (matq[q] * KB + kq[q]) * 288))[c4q[q]] = st[q];
    }
    __syncthreads();
    float acc_i[4] = {0.f, 0.f, 0.f, 0.f};
    float acc_h[4] = {0.f, 0.f, 0.f, 0.f};
#pragma unroll 1
    for (int c = 0; c < NCH; c++) {
        int b = c & 1;
        float4 nx[4];
        if (c + 1 < NCH) {
#pragma unroll
            for (int q = 0; q < 4; q++) {
                const float* src = matq[q] ? g_TWhh : g_Wc;
                nx[q] = ((const float4*)(src + ((c + 1) * KB + kq[q]) * 288))[c4q[q]];
            }
        }
#pragma unroll
        for (int k = 0; k < KB; k++) {
            float wi = sbuf[((b * 2 + 0) * KB + k) * 288 + t];
            float wh = sbuf[((b * 2 + 1) * KB + k) * 288 + t];
            int kk = c * KB + k;
#pragma unroll
            for (int r = 0; r < 4; r++) {
                acc_i[r] = fmaf(ys[r][kk], wi, acc_i[r]);
                acc_h[r] = fmaf(xs[r][kk], wh, acc_h[r]);
            }
        }
        if (c + 1 < NCH) {
            int b2 = b ^ 1;
#pragma unroll
            for (int q = 0; q < 4; q++)
                ((float4*)(sbuf + ((b2 * 2 + matq[q]) * KB + kq[q]) * 288))[c4q[q]] = nx[q];
        }
        __syncthreads();
    }
    if (t < 192) {
        float bb = bih[t] + bhh[t];
#pragma unroll
        for (int r = 0; r < 4; r++) gA[r][t] = acc_i[r] + acc_h[r] + bb;
    } else {
        float bi_n = bih[t], bh_n = bhh[t];
        int h = t - 192;
#pragma unroll
        for (int r = 0; r < 4; r++) {
            gA[r][t] = acc_i[r] + bi_n;
            gN[r][h] = acc_h[r] + bh_n;
        }
    }
    __syncthreads();

    // ---- phase C: GRU nonlinearity; stage xnew into ys ----
    for (int f = t; f < 4 * HH; f += 288) {
        int r = f / HH, h = f - r * HH;
        float rr = sigf(gA[r][h]);
        float zz = sigf(gA[r][HH + h]);
        float n = tanhf(gA[r][2 * HH + h] + rr * gN[r][h]);
        float xv = (1.0f - zz) * n + zz * xs[r][h];
        int row = i0 + r;
        g_xC[row * HH + h] = xv;
        xn[row * HH + h] = 0.0f;
        ys[r][h] = xv;
    }
    __syncthreads();

    // ---- phase D: projections GEMM (TA staged, double-buffered) ----
    // staging map: v = t + 288q in [0,384): k = v/48, c4 = v%48
    int kp0 = t / 48, c4p0 = t % 48;                 // q=0 (all threads)
    int kp1 = (t + 288) / 48, c4p1 = (t + 288) % 48; // q=1 (t<96 only)
    {
        float4 s0 = ((const float4*)(g_TA + kp0 * 192))[c4p0];
        float4 s1;
        if (t < 96) s1 = ((const float4*)(g_TA + kp1 * 192))[c4p1];
        ((float4*)(sbuf + kp0 * 192))[c4p0] = s0;
        if (t < 96) ((float4*)(sbuf + kp1 * 192))[c4p1] = s1;
    }
    __syncthreads();
    float pa[4] = {0.f, 0.f, 0.f, 0.f};
#pragma unroll 1
    for (int c = 0; c < NCH; c++) {
        int b = c & 1;
        float4 n0, n1;
        if (c + 1 < NCH) {
            n0 = ((const float4*)(g_TA + ((c + 1) * KB + kp0) * 192))[c4p0];
            if (t < 96) n1 = ((const float4*)(g_TA + ((c + 1) * KB + kp1) * 192))[c4p1];
        }
        if (t < 192) {
#pragma unroll
            for (int k = 0; k < KB; k++) {
                float w = sbuf[(b * KB + k) * 192 + t];
                int kk = c * KB + k;
#pragma unroll
                for (int r = 0; r < 4; r++) pa[r] = fmaf(ys[r][kk], w, pa[r]);
            }
        }
        if (c + 1 < NCH) {
            int b2 = b ^ 1;
            ((float4*)(sbuf + (b2 * KB + kp0) * 192))[c4p0] = n0;
            if (t < 96) ((float4*)(sbuf + (b2 * KB + kp1) * 192))[c4p1] = n1;
        }
        __syncthreads();
    }
    if (t < 192) {
        float bb = (t < HH) ? ba1[t] : 0.0f;
#pragma unroll
        for (int r = 0; r < 4; r++) {
            float v = 0.5f * (pa[r] + bb);
            int row = i0 + r;
            if (t < HH) g_hip[row * HH + t] = v;
            else        g_hjp[row * HH + t - HH] = v;
        }
    }
}

// ---------------- K4: attention + x = coeffs @ xC, j-split 2 ------------
__global__ void __launch_bounds__(256) k_att(int sel,
                                             const int* __restrict__ adj,
                                             const float* __restrict__ Wa2,
                                             const float* __restrict__ ba2) {
    const float* xg = g_xC;                 // GRU output
    float* xn = sel ? g_xA : g_xB;
    const int rg = blockIdx.x >> 1;
    const int jbase = (blockIdx.x & 1) * (NN / 2);
    const int i0 = rg * BI;
    int tid = threadIdx.x, lane = tid & 31, w = tid >> 5;
    __shared__ float hi_s[BI][HH];
    __shared__ float w_s[HH];
    __shared__ float tile[TJ][HH + 1];
    __shared__ float c2[TJ][BI];
    __shared__ float bs_s;

    if (tid < HH) w_s[tid] = 0.5f * Wa2[tid];
    for (int f = tid; f < BI * HH; f += 256) {
        int il = f / HH, k = f - il * HH;
        hi_s[il][k] = g_hip[(i0 + il) * HH + k];
    }
    __syncthreads();
    if (tid == 0) {
        float s = ba2[0];
        for (int k = 0; k < HH; k++) s += w_s[k];
        bs_s = s;
    }
    __syncthreads();

    const int jl = tid >> 2, q = tid & 3;
    float wr[24];
#pragma unroll
    for (int s = 0; s < 24; s++) wr[s] = w_s[q * 24 + s];
    const float base = bs_s;

    float a0[BI], a1[BI], a2[BI];
#pragma unroll
    for (int il = 0; il < BI; il++) { a0[il] = 0.f; a1[il] = 0.f; a2[il] = 0.f; }

    for (int jt = 0; jt < NN / 2; jt += TJ) {
        for (int f = tid; f < TJ * HH; f += 256) {
            int r = f / HH, k = f - r * HH;
            tile[r][k] = g_hjp[(jbase + jt) * HH + f];
        }
        __syncthreads();
        float p[BI];
#pragma unroll
        for (int il = 0; il < BI; il++) p[il] = 0.0f;
#pragma unroll 4
        for (int s = 0; s < 24; s++) {
            int k = q * 24 + s;
            float tj = tile[jl][k];
            float ws = wr[s];
#pragma unroll
            for (int il = 0; il < BI; il++)
                p[il] = fmaf(ws, tanhfast(hi_s[il][k] + tj), p[il]);
        }
#pragma unroll
        for (int il = 0; il < BI; il++) {
            p[il] += __shfl_xor_sync(0xffffffffu, p[il], 1);
            p[il] += __shfl_xor_sync(0xffffffffu, p[il], 2);
        }
        if (q == 0) {
            int j = jbase + jt + jl;
#pragma unroll
            for (int il = 0; il < BI; il++) {
                int a = adj[(long)(i0 + il) * NN + j];
                float sv = p[il] + base;
                c2[jl][il] = a ? fmaf(0.5f, tanhfast(0.5f * sv), 0.5f) : 0.0f;
            }
        }
        __syncthreads();
        for (int f = tid; f < TJ * HH; f += 256) {
            int r = f / HH, k = f - r * HH;
            tile[r][k] = xg[(jbase + jt) * HH + f];
        }
        __syncthreads();
#pragma unroll
        for (int u = 0; u < 8; u++) {
            int jj = w * 8 + u;
            float t0 = tile[jj][lane];
            float t1 = tile[jj][lane + 32];
            float t2 = tile[jj][lane + 64];
#pragma unroll
            for (int il = 0; il < BI; il++) {
                float c = c2[jj][il];
                a0[il] = fmaf(c, t0, a0[il]);
                a1[il] = fmaf(c, t1, a1[il]);
                a2[il] = fmaf(c, t2, a2[il]);
            }
        }
        __syncthreads();
    }
    float* sa = &tile[0][0];
#pragma unroll
    for (int il = 0; il < BI; il++) {
        sa[(w * BI + il) * HH + lane] = a0[il];
        sa[(w * BI + il) * HH + lane + 32] = a1[il];
        sa[(w * BI + il) * HH + lane + 64] = a2[il];
    }
    __syncthreads();
    for (int f = tid; f < BI * HH; f += 256) {
        int il = f / HH, h = f - il * HH;
        float s = 0.0f;
#pragma unroll
        for (int ww = 0; ww < 8; ww++) s += sa[(ww * BI + il) * HH + h];
        atomicAdd(&xn[(i0 + il) * HH + h], s);
    }
}

// ---------------- K5: output head, 4 rows per block ---------------------
__global__ void k_out(int sel,
                      const float* __restrict__ bo1, const float* __restrict__ bo2,
                      const float* __restrict__ Wp1, const float* __restrict__ bp1,
                      const float* __restrict__ Wp2, const float* __restrict__ bp2,
                      float* __restrict__ out) {
    const float* xc = sel ? g_xB : g_xA;
    int i0 = blockIdx.x * 4, h = threadIdx.x, lane = h & 31, w = h >> 5;
    __shared__ float xs[4][HH], y1[4][HH], y2[4][HH];
#pragma unroll
    for (int r = 0; r < 4; r++) xs[r][h] = xc[(i0 + r) * HH + h];
    __syncthreads();
    {
        float bb = bo1[h];
        float a[4] = {bb, bb, bb, bb};
#pragma unroll 2
        for (int kb = 0; kb < HH; kb += 8) {
            float wbuf[8];
#pragma unroll
            for (int u = 0; u < 8; u++) wbuf[u] = g_TO1[(kb + u) * HH + h];
#pragma unroll
            for (int u = 0; u < 8; u++) {
#pragma unroll
                for (int r = 0; r < 4; r++) a[r] = fmaf(xs[r][kb + u], wbuf[u], a[r]);
            }
        }
#pragma unroll
        for (int r = 0; r < 4; r++) y1[r][h] = leakyf(a[r]);
    }
    __syncthreads();
    {
        float bb = bo2[h];
        float a[4] = {bb, bb, bb, bb};
#pragma unroll 2
        for (int kb = 0; kb < HH; kb += 8) {
            float wbuf[8];
#pragma unroll
            for (int u = 0; u < 8; u++) wbuf[u] = g_TO2[(kb + u) * HH + h];
#pragma unroll
            for (int u = 0; u < 8; u++) {
#pragma unroll
                for (int r = 0; r < 4; r++) a[r] = fmaf(y1[r][kb + u], wbuf[u], a[r]);
            }
        }
#pragma unroll
        for (int r = 0; r < 4; r++) y2[r][h] = leakyf(a[r]);
    }
    __syncthreads();
    if (w < 2) {
        const float* Wp = (w == 0) ? Wp1 : Wp2;
        float bp = (w == 0) ? bp1[0] : bp2[0];
#pragma unroll
        for (int r = 0; r < 4; r++) {
            float p = y2[r][lane] * Wp[lane] + y2[r][lane + 32] * Wp[lane + 32]
                    + y2[r][lane + 64] * Wp[lane + 64];
#pragma unroll
            for (int o = 16; o > 0; o >>= 1) p += __shfl_xor_sync(0xffffffffu, p, o);
            if (lane == 0) out[w * NN + i0 + r] = sigf(p + bp);
        }
    }
}

// ---------------- launch ----------------
extern "C" void kernel_launch(void* const* d_in, const int* in_sizes, int n_in,
                              void* d_out, int out_size) {
    const float* x      = (const float*)d_in[0];
    const int*   ei     = (const int*)d_in[1];   // int32 (JAX x64 disabled)
    const int*   adj    = (const int*)d_in[2];
    const float* W_init = (const float*)d_in[3];
    const float* b_init = (const float*)d_in[4];
    const float* W_ggc  = (const float*)d_in[5];
    const float* W_ih   = (const float*)d_in[6];
    const float* W_hh   = (const float*)d_in[7];
    const float* b_ih   = (const float*)d_in[8];
    const float* b_hh   = (const float*)d_in[9];
    const float* Wa1    = (const float*)d_in[10];
    const float* ba1    = (const float*)d_in[11];
    const float* Wa2    = (const float*)d_in[12];
    const float* ba2    = (const float*)d_in[13];
    const float* Wo1    = (const float*)d_in[14];
    const float* bo1    = (const float*)d_in[15];
    const float* Wo2    = (const float*)d_in[16];
    const float* bo2    = (const float*)d_in[17];
    const float* Wp1    = (const float*)d_in[18];
    const float* bp1    = (const float*)d_in[19];
    const float* Wp2    = (const float*)d_in[20];
    const float* bp2    = (const float*)d_in[21];
    float* out = (float*)d_out;

    k_setup<<<96 + 342, 288>>>(x, W_init, b_init, W_ih, W_hh, Wa1, Wo1, Wo2);
    k_wcomb<<<HH, 288>>>(W_ggc);
    k_scanfill<<<1, NN>>>(ei);

    for (int t = 0; t < 2; t++) {
        int sel = t & 1;   // x in A when t==0, in B when t==1
        k_grup<<<NN / 4, 288>>>(sel, b_ih, b_hh, ba1);
        k_att<<<NN / BI * 2, 256>>>(sel, adj, Wa2, ba2);
    }
    k_out<<<NN / 4, HH>>>(0, bo1, bo2, Wp1, bp1, Wp2, bp2, out);
}

// round 17
// speedup vs baseline: 1.8788x; 1.0525x over previous
#include <cuda_runtime.h>
#include <cuda_bf16.h>

#define NN 1024
#define HH 96
#define EE 16384
#define TJ 64
#define BI 8
#define KB 8          // k-chunk for smem staging
#define NCH (HH / KB) // 12 chunks

// ---------------- device scratch (no allocation allowed) ----------------
__device__ float g_xA[NN * HH];
__device__ float g_xB[NN * HH];
__device__ float g_xC[NN * HH];    // GRU output (k_att phase-2 source)
__device__ float g_hip[NN * HH];
__device__ float g_hjp[NN * HH];
__device__ int   g_off[NN + 1];
__device__ int   g_csr[EE];
__device__ float g_TWih[HH * 288]; // [k][gate*96+h]  (used only to build Wcomb)
__device__ float g_TWhh[HH * 288];
__device__ float g_Wc[HH * 288];   // Wcomb[k][t] = sum_j Wggc[k][j]*Wih[t][j]
__device__ float g_TA[HH * 192];
__device__ float g_TO1[HH * HH];
__device__ float g_TO2[HH * HH];

__device__ __forceinline__ float sigf(float v) {
    return __fdividef(1.0f, 1.0f + __expf(-v));
}
__device__ __forceinline__ float leakyf(float v) {
    return v >= 0.0f ? v : 0.01f * v;
}
__device__ __forceinline__ float tanhfast(float v) {
    float y;
    asm("tanh.approx.f32 %0, %1;" : "=f"(y) : "f"(v));
    return y;
}

// ---------------- K0: weight transpose + input projection ---------------
__global__ void k_setup(const float* __restrict__ x,
                        const float* __restrict__ Wi, const float* __restrict__ bi,
                        const float* __restrict__ Wih, const float* __restrict__ Whh,
                        const float* __restrict__ Wa1,
                        const float* __restrict__ Wo1, const float* __restrict__ Wo2) {
    int b = blockIdx.x, t = threadIdx.x;
    if (b < HH) {
        int k = b;
        g_TWih[k * 288 + t] = Wih[t * HH + k];
        g_TWhh[k * 288 + t] = Whh[t * HH + k];
        if (t < 192)
            g_TA[k * 192 + t] = (t < HH) ? Wa1[t * 192 + k]
                                         : Wa1[(t - HH) * 192 + HH + k];
        if (t < HH) {
            g_TO1[k * HH + t] = Wo1[t * HH + k];
            g_TO2[k * HH + t] = Wo2[t * HH + k];
        }
    } else {
        int rr = t / HH, h = t - rr * HH;
        int i = (b - HH) * 3 + rr;
        if (i < NN) {
            float a = bi[h];
#pragma unroll
            for (int c = 0; c < 9; c++) a = fmaf(x[i * 10 + c], Wi[h * 9 + c], a);
            g_xA[i * HH + h] = leakyf(a);
        }
    }
}

// ---------------- K0b: Wcomb = Wggc @ Wih^T (needs TWih) ----------------
__global__ void k_wcomb(const float* __restrict__ Wg) {
    int k = blockIdx.x, t = threadIdx.x;
    __shared__ float swg[HH];
    if (t < HH) swg[t] = Wg[k * HH + t];
    __syncthreads();
    float acc = 0.0f;
#pragma unroll 2
    for (int jb = 0; jb < HH; jb += 8) {
        float wv[8];
#pragma unroll
        for (int u = 0; u < 8; u++) wv[u] = g_TWih[(jb + u) * 288 + t];
#pragma unroll
        for (int u = 0; u < 8; u++) acc = fmaf(swg[jb + u], wv[u], acc);
    }
    g_Wc[k * 288 + t] = acc;
}

// ---------------- K1: degree count + scan + CSR fill, one block ---------
__global__ void k_scanfill(const int* __restrict__ ei) {
    __shared__ int cnt[NN];
    __shared__ int cur[NN];
    __shared__ int wsum[32];
    int t = threadIdx.x, lane = t & 31, wid = t >> 5;
    cnt[t] = 0;
    __syncthreads();
    for (int e = t; e < EE; e += NN) atomicAdd(&cnt[ei[EE + e]], 1);
    __syncthreads();
    int d = cnt[t], v = d;
#pragma unroll
    for (int o = 1; o < 32; o <<= 1) {
        int u = __shfl_up_sync(0xffffffffu, v, o);
        if (lane >= o) v += u;
    }
    if (lane == 31) wsum[wid] = v;
    __syncthreads();
    if (wid == 0) {
        int s = wsum[lane];
#pragma unroll
        for (int o = 1; o < 32; o <<= 1) {
            int u = __shfl_up_sync(0xffffffffu, s, o);
            if (lane >= o) s += u;
        }
        wsum[lane] = s;
    }
    __syncthreads();
    int incl = v + (wid ? wsum[wid - 1] : 0);
    g_off[t + 1] = incl;
    if (t == 0) g_off[0] = 0;
    cur[t] = incl - d;
    __syncthreads();
    for (int e = t; e < EE; e += NN) {
        int s = ei[e], tg = ei[EE + e];
        int p = atomicAdd(&cur[tg], 1);
        g_csr[p] = s;
    }
}

// ---------------- K2: gather + GRU + projections, smem-staged GEMMs -----
__global__ void __launch_bounds__(288) k_grup(int sel,
                          const float* __restrict__ bih, const float* __restrict__ bhh,
                          const float* __restrict__ ba1) {
    const float* xc = sel ? g_xB : g_xA;
    float* xn = sel ? g_xA : g_xB;
    int t = threadIdx.x;
    int i0 = blockIdx.x * 4;
    __shared__ __align__(16) float ys[4][HH];
    __shared__ __align__(16) float xs[4][HH];
    __shared__ __align__(16) float gA[4][288];
    __shared__ __align__(16) float gN[4][HH];
    __shared__ __align__(16) float sbuf[2 * 2 * KB * 288];

    float4* sP = (float4*)&gA[0][0];
    if (t < 192) {
        int r = t / 48, rem = t % 48, seg = rem / 24, h4 = rem % 24;
        int row = i0 + r;
        int beg = g_off[row], end = g_off[row + 1];
        int d = end - beg, mid = beg + (d >> 1);
        int s = seg ? mid : beg;
        int e = seg ? end : mid;
        float4 a0 = {0.f, 0.f, 0.f, 0.f}, a1 = {0.f, 0.f, 0.f, 0.f};
        int ee = s;
        for (; ee + 1 < e; ee += 2) {
            int j0 = g_csr[ee], j1 = g_csr[ee + 1];
            float4 v0 = ((const float4*)(xc + j0 * HH))[h4];
            float4 v1 = ((const float4*)(xc + j1 * HH))[h4];
            a0.x += v0.x; a0.y += v0.y; a0.z += v0.z; a0.w += v0.w;
            a1.x += v1.x; a1.y += v1.y; a1.z += v1.z; a1.w += v1.w;
        }
        if (ee < e) {
            int j0 = g_csr[ee];
            float4 v0 = ((const float4*)(xc + j0 * HH))[h4];
            a0.x += v0.x; a0.y += v0.y; a0.z += v0.z; a0.w += v0.w;
        }
        a0.x += a1.x; a0.y += a1.y; a0.z += a1.z; a0.w += a1.w;
        sP[(seg * 4 + r) * 24 + h4] = a0;
    } else {
        int u = t - 192;
        int r = u / 24, h4 = u % 24;
        ((float4*)&xs[r][0])[h4] = ((const float4*)(xc + (i0 + r) * HH))[h4];
    }
    __syncthreads();
    if (t < 96) {
        int r = t / 24, h4 = t % 24;
        int row = i0 + r;
        int d = g_off[row + 1] - g_off[row];
        float inv = __fdividef(1.0f, (float)(d > 1 ? d : 1));
        float4 a = sP[(0 * 4 + r) * 24 + h4];
        float4 b = sP[(1 * 4 + r) * 24 + h4];
        float4 o;
        o.x = (a.x + b.x) * inv; o.y = (a.y + b.y) * inv;
        o.z = (a.z + b.z) * inv; o.w = (a.w + b.w) * inv;
        ((float4*)&ys[r][0])[h4] = o;
    }
    __syncthreads();

    int matq[4], kq[4], c4q[4];
#pragma unroll
    for (int q = 0; q < 4; q++) {
        int v = t + 288 * q;
        matq[q] = v / 576;
        int rem = v - matq[q] * 576;
        kq[q] = rem / 72;
        c4q[q] = rem - kq[q] * 72;
    }
    {
        float4 st[4];
#pragma unroll
        for (int q = 0; q < 4; q++) {
            const float* src = matq[q] ? g_TWhh : g_Wc;
            st[q] = ((const float4*)(src + kq[q] * 288))[c4q[q]];
        }
#pragma unroll
        for (int q = 0; q < 4; q++)
            ((float4*)(sbuf + (matq[q] * KB + kq[q]) * 288))[c4q[q]] = st[q];
    }
    __syncthreads();
    float acc_i[4] = {0.f, 0.f, 0.f, 0.f};
    float acc_h[4] = {0.f, 0.f, 0.f, 0.f};
#pragma unroll 1
    for (int c = 0; c < NCH; c++) {
        int b = c & 1;
        float4 nx[4];
        if (c + 1 < NCH) {
#pragma unroll
            for (int q = 0; q < 4; q++) {
                const float* src = matq[q] ? g_TWhh : g_Wc;
                nx[q] = ((const float4*)(src + ((c + 1) * KB + kq[q]) * 288))[c4q[q]];
            }
        }
#pragma unroll
        for (int k = 0; k < KB; k++) {
            float wi = sbuf[((b * 2 + 0) * KB + k) * 288 + t];
            float wh = sbuf[((b * 2 + 1) * KB + k) * 288 + t];
            int kk = c * KB + k;
#pragma unroll
            for (int r = 0; r < 4; r++) {
                acc_i[r] = fmaf(ys[r][kk], wi, acc_i[r]);
                acc_h[r] = fmaf(xs[r][kk], wh, acc_h[r]);
            }
        }
        if (c + 1 < NCH) {
            int b2 = b ^ 1;
#pragma unroll
            for (int q = 0; q < 4; q++)
                ((float4*)(sbuf + ((b2 * 2 + matq[q]) * KB + kq[q]) * 288))[c4q[q]] = nx[q];
        }
        __syncthreads();
    }
    if (t < 192) {
        float bb = bih[t] + bhh[t];
#pragma unroll
        for (int r = 0; r < 4; r++) gA[r][t] = acc_i[r] + acc_h[r] + bb;
    } else {
        float bi_n = bih[t], bh_n = bhh[t];
        int h = t - 192;
#pragma unroll
        for (int r = 0; r < 4; r++) {
            gA[r][t] = acc_i[r] + bi_n;
            gN[r][h] = acc_h[r] + bh_n;
        }
    }
    __syncthreads();

    for (int f = t; f < 4 * HH; f += 288) {
        int r = f / HH, h = f - r * HH;
        float rr = sigf(gA[r][h]);
        float zz = sigf(gA[r][HH + h]);
        float n = tanhf(gA[r][2 * HH + h] + rr * gN[r][h]);
        float xv = (1.0f - zz) * n + zz * xs[r][h];
        int row = i0 + r;
        g_xC[row * HH + h] = xv;
        xn[row * HH + h] = 0.0f;
        ys[r][h] = xv;
    }
    __syncthreads();

    int kp0 = t / 48, c4p0 = t % 48;
    int kp1 = (t + 288) / 48, c4p1 = (t + 288) % 48;
    {
        float4 s0 = ((const float4*)(g_TA + kp0 * 192))[c4p0];
        float4 s1;
        if (t < 96) s1 = ((const float4*)(g_TA + kp1 * 192))[c4p1];
        ((float4*)(sbuf + kp0 * 192))[c4p0] = s0;
        if (t < 96) ((float4*)(sbuf + kp1 * 192))[c4p1] = s1;
    }
    __syncthreads();
    float pa[4] = {0.f, 0.f, 0.f, 0.f};
#pragma unroll 1
    for (int c = 0; c < NCH; c++) {
        int b = c & 1;
        float4 n0, n1;
        if (c + 1 < NCH) {
            n0 = ((const float4*)(g_TA + ((c + 1) * KB + kp0) * 192))[c4p0];
            if (t < 96) n1 = ((const float4*)(g_TA + ((c + 1) * KB + kp1) * 192))[c4p1];
        }
        if (t < 192) {
#pragma unroll
            for (int k = 0; k < KB; k++) {
                float w = sbuf[(b * KB + k) * 192 + t];
                int kk = c * KB + k;
#pragma unroll
                for (int r = 0; r < 4; r++) pa[r] = fmaf(ys[r][kk], w, pa[r]);
            }
        }
        if (c + 1 < NCH) {
            int b2 = b ^ 1;
            ((float4*)(sbuf + (b2 * KB + kp0) * 192))[c4p0] = n0;
            if (t < 96) ((float4*)(sbuf + (b2 * KB + kp1) * 192))[c4p1] = n1;
        }
        __syncthreads();
    }
    if (t < 192) {
        float bb = (t < HH) ? ba1[t] : 0.0f;
#pragma unroll
        for (int r = 0; r < 4; r++) {
            float v = 0.5f * (pa[r] + bb);
            int row = i0 + r;
            if (t < HH) g_hip[row * HH + t] = v;
            else        g_hjp[row * HH + t - HH] = v;
        }
    }
}

// ---- cp.async 4B helper (stride-97 dest preserves conflict-free reads) --
__device__ __forceinline__ void stage_tile97(float* dst, const float* __restrict__ src,
                                             int tid) {
#pragma unroll
    for (int u = 0; u < 24; u++) {
        int f = tid + 256 * u;            // 0..6143
        int r = f / HH, k = f - r * HH;
        unsigned sa = (unsigned)__cvta_generic_to_shared(dst + r * 97 + k);
        asm volatile("cp.async.ca.shared.global [%0], [%1], 4;\n"
                     :: "r"(sa), "l"(src + f));
    }
}

// ---------------- K4: attention + x = coeffs @ xC, cp.async overlap -----
__global__ void __launch_bounds__(256) k_att(int sel,
                                             const int* __restrict__ adj,
                                             const float* __restrict__ Wa2,
                                             const float* __restrict__ ba2) {
    extern __shared__ float dynbuf[];
    float* hjt = dynbuf;               // [TJ][97]
    float* xtt = dynbuf + TJ * 97;     // [TJ][97]
    __shared__ float hi_s[BI][HH];
    __shared__ float w_s[HH];
    __shared__ float c2[TJ][BI];
    __shared__ float bs_s;

    const float* xg = g_xC;
    float* xn = sel ? g_xA : g_xB;
    const int rg = blockIdx.x >> 1;
    const int jbase = (blockIdx.x & 1) * (NN / 2);
    const int i0 = rg * BI;
    int tid = threadIdx.x, lane = tid & 31, w = tid >> 5;

    if (tid < HH) w_s[tid] = 0.5f * Wa2[tid];
    for (int f = tid; f < BI * HH; f += 256) {
        int il = f / HH, k = f - il * HH;
        hi_s[il][k] = g_hip[(i0 + il) * HH + k];
    }
    __syncthreads();
    if (tid == 0) {
        float s = ba2[0];
        for (int k = 0; k < HH; k++) s += w_s[k];
        bs_s = s;
    }

    const int jl = tid >> 2, q = tid & 3;
    float wr[24];
#pragma unroll
    for (int s = 0; s < 24; s++) wr[s] = w_s[q * 24 + s];

    float a0[BI], a1[BI], a2[BI];
#pragma unroll
    for (int il = 0; il < BI; il++) { a0[il] = 0.f; a1[il] = 0.f; a2[il] = 0.f; }

    for (int jt = 0; jt < NN / 2; jt += TJ) {
        // stage hj tile, then x tile (x copy overlaps phase-1 compute)
        stage_tile97(hjt, g_hjp + (jbase + jt) * HH, tid);
        asm volatile("cp.async.commit_group;");
        stage_tile97(xtt, xg + (jbase + jt) * HH, tid);
        asm volatile("cp.async.commit_group;");
        asm volatile("cp.async.wait_group 1;");   // hj ready, x in flight
        __syncthreads();
        // phase 1: p[il] = sum_k w_k tanh(hi+hj)
        float p[BI];
#pragma unroll
        for (int il = 0; il < BI; il++) p[il] = 0.0f;
#pragma unroll 4
        for (int s = 0; s < 24; s++) {
            int k = q * 24 + s;
            float tj = hjt[jl * 97 + k];
            float ws = wr[s];
#pragma unroll
            for (int il = 0; il < BI; il++)
                p[il] = fmaf(ws, tanhfast(hi_s[il][k] + tj), p[il]);
        }
#pragma unroll
        for (int il = 0; il < BI; il++) {
            p[il] += __shfl_xor_sync(0xffffffffu, p[il], 1);
            p[il] += __shfl_xor_sync(0xffffffffu, p[il], 2);
        }
        if (q == 0) {
            int j = jbase + jt + jl;
            float base = bs_s;
#pragma unroll
            for (int il = 0; il < BI; il++) {
                int a = adj[(long)(i0 + il) * NN + j];
                float sv = p[il] + base;
                c2[jl][il] = a ? fmaf(0.5f, tanhfast(0.5f * sv), 0.5f) : 0.0f;
            }
        }
        asm volatile("cp.async.wait_group 0;");   // x tile ready
        __syncthreads();                           // publishes c2 + x
        // phase 2: warp w owns j's [w*8, w*8+8)
#pragma unroll
        for (int u = 0; u < 8; u++) {
            int jj = w * 8 + u;
            float t0 = xtt[jj * 97 + lane];
            float t1 = xtt[jj * 97 + lane + 32];
            float t2 = xtt[jj * 97 + lane + 64];
#pragma unroll
            for (int il = 0; il < BI; il++) {
                float c = c2[jj][il];
                a0[il] = fmaf(c, t0, a0[il]);
                a1[il] = fmaf(c, t1, a1[il]);
                a2[il] = fmaf(c, t2, a2[il]);
            }
        }
        __syncthreads();    // before next tile overwrites buffers
    }
    float* sa = hjt;        // alias scratch for the cross-warp combine
#pragma unroll
    for (int il = 0; il < BI; il++) {
        sa[(w * BI + il) * HH + lane] = a0[il];
        sa[(w * BI + il) * HH + lane + 32] = a1[il];
        sa[(w * BI + il) * HH + lane + 64] = a2[il];
    }
    __syncthreads();
    for (int f = tid; f < BI * HH; f += 256) {
        int il = f / HH, h = f - il * HH;
        float s = 0.0f;
#pragma unroll
        for (int ww = 0; ww < 8; ww++) s += sa[(ww * BI + il) * HH + h];
        atomicAdd(&xn[(i0 + il) * HH + h], s);
    }
}

// ---------------- K5: output head, 4 rows per block ---------------------
__global__ void k_out(int sel,
                      const float* __restrict__ bo1, const float* __restrict__ bo2,
                      const float* __restrict__ Wp1, const float* __restrict__ bp1,
                      const float* __restrict__ Wp2, const float* __restrict__ bp2,
                      float* __restrict__ out) {
    const float* xc = sel ? g_xB : g_xA;
    int i0 = blockIdx.x * 4, h = threadIdx.x, lane = h & 31, w = h >> 5;
    __shared__ float xs[4][HH], y1[4][HH], y2[4][HH];
#pragma unroll
    for (int r = 0; r < 4; r++) xs[r][h] = xc[(i0 + r) * HH + h];
    __syncthreads();
    {
        float bb = bo1[h];
        float a[4] = {bb, bb, bb, bb};
#pragma unroll 2
        for (int kb = 0; kb < HH; kb += 8) {
            float wbuf[8];
#pragma unroll
            for (int u = 0; u < 8; u++) wbuf[u] = g_TO1[(kb + u) * HH + h];
#pragma unroll
            for (int u = 0; u < 8; u++) {
#pragma unroll
                for (int r = 0; r < 4; r++) a[r] = fmaf(xs[r][kb + u], wbuf[u], a[r]);
            }
        }
#pragma unroll
        for (int r = 0; r < 4; r++) y1[r][h] = leakyf(a[r]);
    }
    __syncthreads();
    {
        float bb = bo2[h];
        float a[4] = {bb, bb, bb, bb};
#pragma unroll 2
        for (int kb = 0; kb < HH; kb += 8) {
            float wbuf[8];
#pragma unroll
            for (int u = 0; u < 8; u++) wbuf[u] = g_TO2[(kb + u) * HH + h];
#pragma unroll
            for (int u = 0; u < 8; u++) {
#pragma unroll
                for (int r = 0; r < 4; r++) a[r] = fmaf(y1[r][kb + u], wbuf[u], a[r]);
            }
        }
#pragma unroll
        for (int r = 0; r < 4; r++) y2[r][h] = leakyf(a[r]);
    }
    __syncthreads();
    if (w < 2) {
        const float* Wp = (w == 0) ? Wp1 : Wp2;
        float bp = (w == 0) ? bp1[0] : bp2[0];
#pragma unroll
        for (int r = 0; r < 4; r++) {
            float p = y2[r][lane] * Wp[lane] + y2[r][lane + 32] * Wp[lane + 32]
                    + y2[r][lane + 64] * Wp[lane + 64];
#pragma unroll
            for (int o = 16; o > 0; o >>= 1) p += __shfl_xor_sync(0xffffffffu, p, o);
            if (lane == 0) out[w * NN + i0 + r] = sigf(p + bp);
        }
    }
}

// ---------------- launch ----------------
extern "C" void kernel_launch(void* const* d_in, const int* in_sizes, int n_in,
                              void* d_out, int out_size) {
    const float* x      = (const float*)d_in[0];
    const int*   ei     = (const int*)d_in[1];   // int32 (JAX x64 disabled)
    const int*   adj    = (const int*)d_in[2];
    const float* W_init = (const float*)d_in[3];
    const float* b_init = (const float*)d_in[4];
    const float* W_ggc  = (const float*)d_in[5];
    const float* W_ih   = (const float*)d_in[6];
    const float* W_hh   = (const float*)d_in[7];
    const float* b_ih   = (const float*)d_in[8];
    const float* b_hh   = (const float*)d_in[9];
    const float* Wa1    = (const float*)d_in[10];
    const float* ba1    = (const float*)d_in[11];
    const float* Wa2    = (const float*)d_in[12];
    const float* ba2    = (const float*)d_in[13];
    const float* Wo1    = (const float*)d_in[14];
    const float* bo1    = (const float*)d_in[15];
    const float* Wo2    = (const float*)d_in[16];
    const float* bo2    = (const float*)d_in[17];
    const float* Wp1    = (const float*)d_in[18];
    const float* bp1    = (const float*)d_in[19];
    const float* Wp2    = (const float*)d_in[20];
    const float* bp2    = (const float*)d_in[21];
    float* out = (float*)d_out;

    const int att_smem = 2 * TJ * 97 * (int)sizeof(float);   // 49664 B
    cudaFuncSetAttribute(k_att, cudaFuncAttributeMaxDynamicSharedMemorySize, att_smem);

    k_setup<<<96 + 342, 288>>>(x, W_init, b_init, W_ih, W_hh, Wa1, Wo1, Wo2);
    k_wcomb<<<HH, 288>>>(W_ggc);
    k_scanfill<<<1, NN>>>(ei);

    for (int t = 0; t < 2; t++) {
        int sel = t & 1;   // x in A when t==0, in B when t==1
        k_grup<<<NN / 4, 288>>>(sel, b_ih, b_hh, ba1);
        k_att<<<NN / BI * 2, 256, att_smem>>>(sel, adj, Wa2, ba2);
    }
    k_out<<<NN / 4, HH>>>(0, bo1, bo2, Wp1, bp1, Wp2, bp2, out);
}